// round 2
// baseline (speedup 1.0000x reference)
#include <cuda_runtime.h>
#include <math.h>
#include <float.h>

// Problem constants
#define BB 2
#define TT 512
#define DM 3584
#define NQ 28
#define NKV 4
#define GRP 7
#define HH 128
#define SCACHE 3584
#define SEQ 4096            // SCACHE + TT
#define MTOT (BB*TT)        // 1024

#define OUT_ELEMS (BB*TT*DM)           // 3,670,016
#define KV_ELEMS  (BB*SEQ*NKV*HH)      // 4,194,304

// Scratch (static device arrays; no allocation allowed)
__device__ float g_q[BB*TT*NQ*HH];     // raw q proj, then roped+scaled in place
__device__ float g_enc[BB*TT*NQ*HH];   // attention output (pre out-proj)

// ---------------------------------------------------------------------------
// Cache copy: cache_k/cache_v -> output cached regions, rows s < SCACHE
// ---------------------------------------------------------------------------
__global__ void cache_copy_kernel(const float4* __restrict__ ck,
                                  const float4* __restrict__ cv,
                                  float4* __restrict__ outk,
                                  float4* __restrict__ outv)
{
    const int per_b = SCACHE*NKV*HH/4;       // float4 per batch per tensor
    const int n4 = BB * per_b;
    for (int idx = blockIdx.x*blockDim.x + threadIdx.x; idx < n4;
         idx += gridDim.x*blockDim.x) {
        int b = idx / per_b;
        int r = idx - b*per_b;
        size_t o = (size_t)b*(SEQ*NKV*HH/4) + r;
        outk[o] = ck[idx];
        outv[o] = cv[idx];
    }
}

// ---------------------------------------------------------------------------
// QKV projection GEMM: per-head C[1024,128] = X[1024,3584] @ W_head[3584,128]
// blockIdx.y = head z: 0..27 q, 28..31 k, 32..35 v
// BM=128, BN=128, BK=8, 256 threads, 8x8 register tile
// ---------------------------------------------------------------------------
__global__ __launch_bounds__(256) void qkv_gemm_kernel(
    const float* __restrict__ x,
    const float* __restrict__ wq, const float* __restrict__ wk,
    const float* __restrict__ wv,
    float* __restrict__ outk, float* __restrict__ outv)
{
    __shared__ __align__(16) float As[8*128];
    __shared__ __align__(16) float Bs[8*128];

    int m0 = blockIdx.x * 128;
    int hz = blockIdx.y;
    const float* Bp;
    if (hz < NQ)            Bp = wq + (size_t)hz*DM*HH;
    else if (hz < NQ+NKV)   Bp = wk + (size_t)(hz-NQ)*DM*HH;
    else                    Bp = wv + (size_t)(hz-NQ-NKV)*DM*HH;

    int tid = threadIdx.x;
    int arow = tid >> 1, acol = (tid & 1) * 4;
    int brow = tid >> 5, bcol = (tid & 31) * 4;
    int ty = tid >> 4, tx = tid & 15;

    float acc[8][8];
    #pragma unroll
    for (int i = 0; i < 8; i++)
        #pragma unroll
        for (int j = 0; j < 8; j++) acc[i][j] = 0.f;

    const float* Aptr = x + (size_t)(m0 + arow)*DM + acol;
    const float* Bptr = Bp + (size_t)brow*HH + bcol;

    for (int k0 = 0; k0 < DM; k0 += 8) {
        float4 av = *(const float4*)(Aptr + k0);
        float4 bv = *(const float4*)(Bptr + (size_t)k0*HH);
        As[(acol+0)*128 + arow] = av.x;
        As[(acol+1)*128 + arow] = av.y;
        As[(acol+2)*128 + arow] = av.z;
        As[(acol+3)*128 + arow] = av.w;
        *(float4*)&Bs[brow*128 + bcol] = bv;
        __syncthreads();
        #pragma unroll
        for (int k = 0; k < 8; k++) {
            float a[8], b[8];
            *(float4*)&a[0] = *(const float4*)&As[k*128 + ty*8];
            *(float4*)&a[4] = *(const float4*)&As[k*128 + ty*8 + 4];
            *(float4*)&b[0] = *(const float4*)&Bs[k*128 + tx*8];
            *(float4*)&b[4] = *(const float4*)&Bs[k*128 + tx*8 + 4];
            #pragma unroll
            for (int i = 0; i < 8; i++)
                #pragma unroll
                for (int j = 0; j < 8; j++)
                    acc[i][j] += a[i]*b[j];
        }
        __syncthreads();
    }

    // epilogue: write raw projections (rope applied by a later kernel)
    #pragma unroll
    for (int i = 0; i < 8; i++) {
        int m = m0 + ty*8 + i;
        int b = m / TT, t = m - b*TT;
        float* dst;
        if (hz < NQ)
            dst = g_q + ((size_t)m*NQ + hz)*HH;
        else if (hz < NQ+NKV)
            dst = outk + (((size_t)(b*SEQ + SCACHE + t))*NKV + (hz-NQ))*HH;
        else
            dst = outv + (((size_t)(b*SEQ + SCACHE + t))*NKV + (hz-NQ-NKV))*HH;
        *(float4*)(dst + tx*8)     = make_float4(acc[i][0],acc[i][1],acc[i][2],acc[i][3]);
        *(float4*)(dst + tx*8 + 4) = make_float4(acc[i][4],acc[i][5],acc[i][6],acc[i][7]);
    }
}

// ---------------------------------------------------------------------------
// mRoPE: in-place on g_q (with q-scale) and on outk rows s >= SCACHE.
// One thread per (b, t, i<64); handles the (i, i+64) pair for all heads.
// ---------------------------------------------------------------------------
__global__ void rope_kernel(const int* __restrict__ positions,
                            float* __restrict__ outk)
{
    int idx = blockIdx.x*blockDim.x + threadIdx.x;
    if (idx >= BB*TT*64) return;
    int i = idx & 63;
    int t = (idx >> 6) & (TT-1);
    int b = idx >> 15;

    int j = (i < 16) ? 0 : ((i < 40) ? 1 : 2);   // mrope section axis
    int pos = positions[(j*BB + b)*TT + t];

    // inv_freq = theta^(-2i/128); theta = 1e6, log2(1e6) = 19.931568569324174
    double inv = exp2(((double)(-2*i) / 128.0) * 19.931568569324174);
    double ang = (double)pos * inv;
    double sd, cd;
    sincos(ang, &sd, &cd);
    float c = (float)cd, s = (float)sd;
    const float qs = 0.08838834764831845f;   // 128^-0.5

    size_t qbase = ((size_t)(b*TT + t))*NQ*HH;
    #pragma unroll 4
    for (int n = 0; n < NQ; n++) {
        float x1 = g_q[qbase + n*HH + i];
        float x2 = g_q[qbase + n*HH + i + 64];
        g_q[qbase + n*HH + i]      = (x1*c - x2*s)*qs;
        g_q[qbase + n*HH + i + 64] = (x2*c + x1*s)*qs;
    }
    size_t kbase = ((size_t)(b*SEQ + SCACHE + t))*NKV*HH;
    #pragma unroll
    for (int kh = 0; kh < NKV; kh++) {
        float x1 = outk[kbase + kh*HH + i];
        float x2 = outk[kbase + kh*HH + i + 64];
        outk[kbase + kh*HH + i]      = x1*c - x2*s;
        outk[kbase + kh*HH + i + 64] = x2*c + x1*s;
    }
}

// ---------------------------------------------------------------------------
// Flash attention: block = (64 queries, one q-head, one batch)
// chunks of 64 keys over S=4096; fp32 throughout; causal mask analytic.
// Thread layout 16x16: logits rows r=ty+16i, cols c=tx+16jc; PV cols tx+16j.
// V transposed in smem so both GEMM phases are k-major float4 reads.
// ---------------------------------------------------------------------------
#define QS_STRIDE 132
#define KC_STRIDE 132
#define VT_STRIDE 68
#define PS_STRIDE 68
#define ATTN_SMEM ((64*QS_STRIDE + 64*KC_STRIDE + 128*VT_STRIDE + 64*PS_STRIDE)*4)

__global__ __launch_bounds__(256) void attn_kernel(
    const float* __restrict__ kc, const float* __restrict__ vc)
{
    extern __shared__ __align__(16) float sm[];
    float* Qs = sm;                          // [64][132]
    float* Kc = Qs + 64*QS_STRIDE;           // [64][132]
    float* Vt = Kc + 64*KC_STRIDE;           // [128][68]  (transposed)
    float* Ps = Vt + 128*VT_STRIDE;          // [64][68]

    int t0 = blockIdx.x * 64;
    int n  = blockIdx.y;
    int b  = blockIdx.z;
    int kh = n / GRP;
    int tid = threadIdx.x;
    int ty = tid >> 4, tx = tid & 15;

    // load Q tile (roped+scaled)
    for (int l = tid; l < 64*32; l += 256) {
        int r = l >> 5, h = (l & 31) * 4;
        *(float4*)&Qs[r*QS_STRIDE + h] =
            *(const float4*)&g_q[(((size_t)(b*TT + t0 + r))*NQ + n)*HH + h];
    }

    float m_i[4], l_i[4], acc[4][8];
    #pragma unroll
    for (int i = 0; i < 4; i++) {
        m_i[i] = -FLT_MAX; l_i[i] = 0.f;
        #pragma unroll
        for (int j = 0; j < 8; j++) acc[i][j] = 0.f;
    }

    int nchunks = (SCACHE + t0 + 64) >> 6;   // exact: t0 multiple of 64
    int vk = tid & 63, vh0 = (tid >> 6) * 32;

    for (int ch = 0; ch < nchunks; ch++) {
        int s0 = ch * 64;
        __syncthreads();   // prior PV done before overwriting K/V/P
        // K chunk
        for (int l = tid; l < 64*32; l += 256) {
            int c = l >> 5, h = (l & 31) * 4;
            *(float4*)&Kc[c*KC_STRIDE + h] =
                *(const float4*)&kc[(((size_t)(b*SEQ + s0 + c))*NKV + kh)*HH + h];
        }
        // V chunk, transposed into Vt[h][k]
        {
            const float* vrow = &vc[(((size_t)(b*SEQ + s0 + vk))*NKV + kh)*HH + vh0];
            #pragma unroll
            for (int qd = 0; qd < 8; qd++) {
                float4 vv = *(const float4*)(vrow + qd*4);
                Vt[(vh0 + qd*4 + 0)*VT_STRIDE + vk] = vv.x;
                Vt[(vh0 + qd*4 + 1)*VT_STRIDE + vk] = vv.y;
                Vt[(vh0 + qd*4 + 2)*VT_STRIDE + vk] = vv.z;
                Vt[(vh0 + qd*4 + 3)*VT_STRIDE + vk] = vv.w;
            }
        }
        __syncthreads();

        // logits S = Q K^T  (64x64)
        float sv[4][4];
        #pragma unroll
        for (int i = 0; i < 4; i++)
            #pragma unroll
            for (int jc = 0; jc < 4; jc++) sv[i][jc] = 0.f;
        #pragma unroll 4
        for (int h0 = 0; h0 < HH; h0 += 4) {
            float4 qv[4], kv[4];
            #pragma unroll
            for (int i = 0; i < 4; i++)
                qv[i] = *(const float4*)&Qs[(ty + 16*i)*QS_STRIDE + h0];
            #pragma unroll
            for (int jc = 0; jc < 4; jc++)
                kv[jc] = *(const float4*)&Kc[(tx + 16*jc)*KC_STRIDE + h0];
            #pragma unroll
            for (int i = 0; i < 4; i++)
                #pragma unroll
                for (int jc = 0; jc < 4; jc++)
                    sv[i][jc] += qv[i].x*kv[jc].x + qv[i].y*kv[jc].y
                               + qv[i].z*kv[jc].z + qv[i].w*kv[jc].w;
        }

        // mask + online softmax (row groups of 16 lanes share a row set)
        #pragma unroll
        for (int i = 0; i < 4; i++) {
            int smax = SCACHE + t0 + ty + 16*i;   // valid iff s <= smax
            float mx = -FLT_MAX;
            #pragma unroll
            for (int jc = 0; jc < 4; jc++) {
                int s = s0 + tx + 16*jc;
                if (s > smax) sv[i][jc] = -FLT_MAX;
                mx = fmaxf(mx, sv[i][jc]);
            }
            mx = fmaxf(mx, __shfl_xor_sync(0xffffffffu, mx, 1));
            mx = fmaxf(mx, __shfl_xor_sync(0xffffffffu, mx, 2));
            mx = fmaxf(mx, __shfl_xor_sync(0xffffffffu, mx, 4));
            mx = fmaxf(mx, __shfl_xor_sync(0xffffffffu, mx, 8));
            float mnew = fmaxf(m_i[i], mx);
            float corr = __expf(m_i[i] - mnew);
            m_i[i] = mnew;
            float ps = 0.f;
            #pragma unroll
            for (int jc = 0; jc < 4; jc++) {
                float p = __expf(sv[i][jc] - mnew);
                Ps[(ty + 16*i)*PS_STRIDE + tx + 16*jc] = p;
                ps += p;
            }
            ps += __shfl_xor_sync(0xffffffffu, ps, 1);
            ps += __shfl_xor_sync(0xffffffffu, ps, 2);
            ps += __shfl_xor_sync(0xffffffffu, ps, 4);
            ps += __shfl_xor_sync(0xffffffffu, ps, 8);
            l_i[i] = l_i[i]*corr + ps;
            #pragma unroll
            for (int j = 0; j < 8; j++) acc[i][j] *= corr;
        }
        __syncthreads();   // Ps visible to all before PV

        // PV: acc += P @ V (both k-major float4 reads)
        #pragma unroll 4
        for (int k0 = 0; k0 < 64; k0 += 4) {
            float4 pv[4], vv[8];
            #pragma unroll
            for (int i = 0; i < 4; i++)
                pv[i] = *(const float4*)&Ps[(ty + 16*i)*PS_STRIDE + k0];
            #pragma unroll
            for (int j = 0; j < 8; j++)
                vv[j] = *(const float4*)&Vt[(tx + 16*j)*VT_STRIDE + k0];
            #pragma unroll
            for (int i = 0; i < 4; i++)
                #pragma unroll
                for (int j = 0; j < 8; j++)
                    acc[i][j] += pv[i].x*vv[j].x + pv[i].y*vv[j].y
                               + pv[i].z*vv[j].z + pv[i].w*vv[j].w;
        }
    }

    // finalize
    #pragma unroll
    for (int i = 0; i < 4; i++) {
        float inv = 1.f / l_i[i];
        int t = t0 + ty + 16*i;
        size_t base = (((size_t)(b*TT + t))*NQ + n)*HH;
        #pragma unroll
        for (int j = 0; j < 8; j++)
            g_enc[base + tx + 16*j] = acc[i][j]*inv;
    }
}

// ---------------------------------------------------------------------------
// Output projection: out[1024,3584] = enc[1024,3584] @ wo[3584,3584]
// ---------------------------------------------------------------------------
__global__ __launch_bounds__(256) void out_gemm_kernel(
    const float* __restrict__ wo, float* __restrict__ out)
{
    __shared__ __align__(16) float As[8*128];
    __shared__ __align__(16) float Bs[8*128];

    int m0 = blockIdx.x * 128;
    int n0 = blockIdx.y * 128;
    int tid = threadIdx.x;
    int arow = tid >> 1, acol = (tid & 1) * 4;
    int brow = tid >> 5, bcol = (tid & 31) * 4;
    int ty = tid >> 4, tx = tid & 15;

    float acc[8][8];
    #pragma unroll
    for (int i = 0; i < 8; i++)
        #pragma unroll
        for (int j = 0; j < 8; j++) acc[i][j] = 0.f;

    const float* Aptr = g_enc + (size_t)(m0 + arow)*DM + acol;
    const float* Bptr = wo + (size_t)brow*DM + n0 + bcol;

    for (int k0 = 0; k0 < DM; k0 += 8) {
        float4 av = *(const float4*)(Aptr + k0);
        float4 bv = *(const float4*)(Bptr + (size_t)k0*DM);
        As[(acol+0)*128 + arow] = av.x;
        As[(acol+1)*128 + arow] = av.y;
        As[(acol+2)*128 + arow] = av.z;
        As[(acol+3)*128 + arow] = av.w;
        *(float4*)&Bs[brow*128 + bcol] = bv;
        __syncthreads();
        #pragma unroll
        for (int k = 0; k < 8; k++) {
            float a[8], b[8];
            *(float4*)&a[0] = *(const float4*)&As[k*128 + ty*8];
            *(float4*)&a[4] = *(const float4*)&As[k*128 + ty*8 + 4];
            *(float4*)&b[0] = *(const float4*)&Bs[k*128 + tx*8];
            *(float4*)&b[4] = *(const float4*)&Bs[k*128 + tx*8 + 4];
            #pragma unroll
            for (int i = 0; i < 8; i++)
                #pragma unroll
                for (int j = 0; j < 8; j++)
                    acc[i][j] += a[i]*b[j];
        }
        __syncthreads();
    }

    #pragma unroll
    for (int i = 0; i < 8; i++) {
        size_t row = (size_t)(m0 + ty*8 + i)*DM + n0;
        *(float4*)(out + row + tx*8)     = make_float4(acc[i][0],acc[i][1],acc[i][2],acc[i][3]);
        *(float4*)(out + row + tx*8 + 4) = make_float4(acc[i][4],acc[i][5],acc[i][6],acc[i][7]);
    }
}

// ---------------------------------------------------------------------------
// Launch
// ---------------------------------------------------------------------------
extern "C" void kernel_launch(void* const* d_in, const int* in_sizes, int n_in,
                              void* d_out, int out_size)
{
    const float* x         = (const float*)d_in[0];
    const int*   positions = (const int*)d_in[1];
    // d_in[2] = attn_mask (deterministic: cache-all-visible + causal; recomputed analytically)
    const float* cache_k   = (const float*)d_in[3];
    const float* cache_v   = (const float*)d_in[4];
    const float* wq        = (const float*)d_in[5];
    const float* wk        = (const float*)d_in[6];
    const float* wv        = (const float*)d_in[7];
    const float* wo        = (const float*)d_in[8];

    float* out  = (float*)d_out;
    float* outk = out + (size_t)OUT_ELEMS;
    float* outv = outk + (size_t)KV_ELEMS;

    // 1. copy old cache into output cache regions
    cache_copy_kernel<<<1024, 256>>>((const float4*)cache_k, (const float4*)cache_v,
                                     (float4*)outk, (float4*)outv);
    // 2. QKV projections (raw)
    qkv_gemm_kernel<<<dim3(8, 36), 256>>>(x, wq, wk, wv, outk, outv);
    // 3. mRoPE in place (q scaled by H^-0.5)
    rope_kernel<<<(BB*TT*64 + 255)/256, 256>>>(positions, outk);
    // 4. flash attention
    cudaFuncSetAttribute(attn_kernel, cudaFuncAttributeMaxDynamicSharedMemorySize, ATTN_SMEM);
    attn_kernel<<<dim3(TT/64, NQ, BB), 256, ATTN_SMEM>>>(outk, outv);
    // 5. output projection
    out_gemm_kernel<<<dim3(8, 28), 256>>>(wo, out);
}

// round 6
// speedup vs baseline: 1.5052x; 1.5052x over previous
#include <cuda_runtime.h>
#include <math.h>
#include <float.h>
#include <stdint.h>

// Problem constants
#define BB 2
#define TT 512
#define DM 3584
#define NQ 28
#define NKV 4
#define GRP 7
#define HH 128
#define SCACHE 3584
#define SEQ 4096

#define OUT_ELEMS (BB*TT*DM)
#define KV_ELEMS  (BB*SEQ*NKV*HH)

// Scratch
__device__ float g_q[BB*TT*NQ*HH];
__device__ float g_enc[BB*TT*NQ*HH];

__device__ __forceinline__ uint32_t f2tf32(float x) {
    uint32_t r;
    asm("cvt.rna.tf32.f32 %0, %1;" : "=r"(r) : "f"(x));
    return r;
}

__device__ __forceinline__ void mma_tf32(float c[4], const uint32_t a[4], const uint32_t b[2]) {
    asm volatile("mma.sync.aligned.m16n8k8.row.col.f32.tf32.tf32.f32 "
        "{%0,%1,%2,%3}, {%4,%5,%6,%7}, {%8,%9}, {%0,%1,%2,%3};"
        : "+f"(c[0]), "+f"(c[1]), "+f"(c[2]), "+f"(c[3])
        : "r"(a[0]), "r"(a[1]), "r"(a[2]), "r"(a[3]), "r"(b[0]), "r"(b[1]));
}

// ===========================================================================
// Shared mma.sync tf32 GEMM mainloop.
// C[128,128] tile: A row-major [128 x DM] (lda), B row-major [DM x 128] (ldb,
// transposed into smem [n][k]). 256 threads, 8 warps, warp tile 32x64.
// acc[mt][nt][4] per warp.
// ===========================================================================
#define BK 32
#define SSTR 36              // padded k-stride in floats (conflict-free frags)
#define CHUNKS (DM/BK)       // 112

__device__ __forceinline__ void gemm_mma_mainloop(
    const float* __restrict__ Ag, int lda,
    const float* __restrict__ Bg, int ldb,
    float acc[2][8][4])
{
    __shared__ __align__(16) float As[128*SSTR];
    __shared__ __align__(16) float Bs[128*SSTR];
    const uint32_t* Au = (const uint32_t*)As;
    const uint32_t* Bu = (const uint32_t*)Bs;

    int tid = threadIdx.x;
    int wid = tid >> 5, lane = tid & 31;
    int wm = (wid & 3) * 32, wn = (wid >> 2) * 64;
    int g = lane >> 2, tg = lane & 3;

    #pragma unroll
    for (int mt = 0; mt < 2; mt++)
        #pragma unroll
        for (int nt = 0; nt < 8; nt++)
            #pragma unroll
            for (int q = 0; q < 4; q++) acc[mt][nt][q] = 0.f;

    // decomposed prefetch indices
    float4 pa[4];
    float  pb[4][4];

    // --- load chunk 0 ---
    #pragma unroll
    for (int it = 0; it < 4; it++) {
        int idx = it * 256 + tid;
        int m = idx >> 3, kq = idx & 7;
        pa[it] = *(const float4*)(Ag + (size_t)m * lda + kq * 4);
        int n = idx & 127, kc0 = (idx >> 7) * 4;
        #pragma unroll
        for (int q = 0; q < 4; q++)
            pb[it][q] = Bg[(size_t)(kc0 + q) * ldb + n];
    }
    // store chunk 0
    #pragma unroll
    for (int it = 0; it < 4; it++) {
        int idx = it * 256 + tid;
        int m = idx >> 3, kq = idx & 7;
        uint4 av;
        av.x = f2tf32(pa[it].x); av.y = f2tf32(pa[it].y);
        av.z = f2tf32(pa[it].z); av.w = f2tf32(pa[it].w);
        *(uint4*)&As[m * SSTR + kq * 4] = av;
        int n = idx & 127, kc0 = (idx >> 7) * 4;
        uint4 bv;
        bv.x = f2tf32(pb[it][0]); bv.y = f2tf32(pb[it][1]);
        bv.z = f2tf32(pb[it][2]); bv.w = f2tf32(pb[it][3]);
        *(uint4*)&Bs[n * SSTR + kc0] = bv;
    }
    __syncthreads();

    for (int c = 0; c < CHUNKS; c++) {
        // prefetch next chunk to regs
        if (c + 1 < CHUNKS) {
            int k0 = (c + 1) * BK;
            #pragma unroll
            for (int it = 0; it < 4; it++) {
                int idx = it * 256 + tid;
                int m = idx >> 3, kq = idx & 7;
                pa[it] = *(const float4*)(Ag + (size_t)m * lda + k0 + kq * 4);
                int n = idx & 127, kc0 = (idx >> 7) * 4;
                #pragma unroll
                for (int q = 0; q < 4; q++)
                    pb[it][q] = Bg[(size_t)(k0 + kc0 + q) * ldb + n];
            }
        }

        // compute current chunk: 4 ksteps of 8
        #pragma unroll
        for (int ks = 0; ks < 4; ks++) {
            int k = ks * 8;
            uint32_t af[2][4];
            #pragma unroll
            for (int mt = 0; mt < 2; mt++) {
                int r0 = (wm + mt * 16 + g) * SSTR;
                int r1 = (wm + mt * 16 + g + 8) * SSTR;
                af[mt][0] = Au[r0 + k + tg];
                af[mt][1] = Au[r1 + k + tg];
                af[mt][2] = Au[r0 + k + tg + 4];
                af[mt][3] = Au[r1 + k + tg + 4];
            }
            uint32_t bf[8][2];
            #pragma unroll
            for (int nt = 0; nt < 8; nt++) {
                int rb = (wn + nt * 8 + g) * SSTR;
                bf[nt][0] = Bu[rb + k + tg];
                bf[nt][1] = Bu[rb + k + tg + 4];
            }
            #pragma unroll
            for (int mt = 0; mt < 2; mt++)
                #pragma unroll
                for (int nt = 0; nt < 8; nt++)
                    mma_tf32(acc[mt][nt], af[mt], bf[nt]);
        }
        __syncthreads();

        if (c + 1 < CHUNKS) {
            #pragma unroll
            for (int it = 0; it < 4; it++) {
                int idx = it * 256 + tid;
                int m = idx >> 3, kq = idx & 7;
                uint4 av;
                av.x = f2tf32(pa[it].x); av.y = f2tf32(pa[it].y);
                av.z = f2tf32(pa[it].z); av.w = f2tf32(pa[it].w);
                *(uint4*)&As[m * SSTR + kq * 4] = av;
                int n = idx & 127, kc0 = (idx >> 7) * 4;
                uint4 bv;
                bv.x = f2tf32(pb[it][0]); bv.y = f2tf32(pb[it][1]);
                bv.z = f2tf32(pb[it][2]); bv.w = f2tf32(pb[it][3]);
                *(uint4*)&Bs[n * SSTR + kc0] = bv;
            }
            __syncthreads();
        }
    }
}

// ===========================================================================
// QKV projection: blockIdx.y = head z (0..27 q, 28..31 k, 32..35 v)
// ===========================================================================
__global__ __launch_bounds__(256, 2) void qkv_mma_kernel(
    const float* __restrict__ x,
    const float* __restrict__ wq, const float* __restrict__ wk,
    const float* __restrict__ wv,
    float* __restrict__ outk, float* __restrict__ outv)
{
    int m0 = blockIdx.x * 128;
    int hz = blockIdx.y;
    const float* Bg;
    if (hz < NQ)          Bg = wq + (size_t)hz * DM * HH;
    else if (hz < NQ+NKV) Bg = wk + (size_t)(hz - NQ) * DM * HH;
    else                  Bg = wv + (size_t)(hz - NQ - NKV) * DM * HH;

    float acc[2][8][4];
    gemm_mma_mainloop(x + (size_t)m0 * DM, DM, Bg, HH, acc);

    int tid = threadIdx.x;
    int wid = tid >> 5, lane = tid & 31;
    int wm = (wid & 3) * 32, wn = (wid >> 2) * 64;
    int g = lane >> 2, tg = lane & 3;

    #pragma unroll
    for (int mt = 0; mt < 2; mt++) {
        #pragma unroll
        for (int h2 = 0; h2 < 2; h2++) {
            int row = wm + mt * 16 + g + h2 * 8;
            int mg = m0 + row;
            int b = mg / TT, t = mg - b * TT;
            float* dst;
            if (hz < NQ)
                dst = g_q + ((size_t)mg * NQ + hz) * HH;
            else if (hz < NQ+NKV)
                dst = outk + (((size_t)(b * SEQ + SCACHE + t)) * NKV + (hz - NQ)) * HH;
            else
                dst = outv + (((size_t)(b * SEQ + SCACHE + t)) * NKV + (hz - NQ - NKV)) * HH;
            #pragma unroll
            for (int nt = 0; nt < 8; nt++) {
                float2 v = make_float2(acc[mt][nt][h2 * 2], acc[mt][nt][h2 * 2 + 1]);
                *(float2*)(dst + wn + nt * 8 + tg * 2) = v;
            }
        }
    }
}

// ===========================================================================
// Output projection: out[1024,3584] = g_enc @ wo[3584,3584]
// ===========================================================================
__global__ __launch_bounds__(256, 2) void out_mma_kernel(
    const float* __restrict__ wo, float* __restrict__ out)
{
    int m0 = blockIdx.x * 128;
    int n0 = blockIdx.y * 128;

    float acc[2][8][4];
    gemm_mma_mainloop(g_enc + (size_t)m0 * DM, DM, wo + n0, DM, acc);

    int tid = threadIdx.x;
    int wid = tid >> 5, lane = tid & 31;
    int wm = (wid & 3) * 32, wn = (wid >> 2) * 64;
    int g = lane >> 2, tg = lane & 3;

    #pragma unroll
    for (int mt = 0; mt < 2; mt++) {
        #pragma unroll
        for (int h2 = 0; h2 < 2; h2++) {
            int row = wm + mt * 16 + g + h2 * 8;
            float* dst = out + (size_t)(m0 + row) * DM + n0;
            #pragma unroll
            for (int nt = 0; nt < 8; nt++) {
                float2 v = make_float2(acc[mt][nt][h2 * 2], acc[mt][nt][h2 * 2 + 1]);
                *(float2*)(dst + wn + nt * 8 + tg * 2) = v;
            }
        }
    }
}

// ---------------------------------------------------------------------------
// Cache copy
// ---------------------------------------------------------------------------
__global__ void cache_copy_kernel(const float4* __restrict__ ck,
                                  const float4* __restrict__ cv,
                                  float4* __restrict__ outk,
                                  float4* __restrict__ outv)
{
    const int per_b = SCACHE*NKV*HH/4;
    const int n4 = BB * per_b;
    for (int idx = blockIdx.x*blockDim.x + threadIdx.x; idx < n4;
         idx += gridDim.x*blockDim.x) {
        int b = idx / per_b;
        int r = idx - b*per_b;
        size_t o = (size_t)b*(SEQ*NKV*HH/4) + r;
        outk[o] = ck[idx];
        outv[o] = cv[idx];
    }
}

// ---------------------------------------------------------------------------
// mRoPE in place
// ---------------------------------------------------------------------------
__global__ void rope_kernel(const int* __restrict__ positions,
                            float* __restrict__ outk)
{
    int idx = blockIdx.x*blockDim.x + threadIdx.x;
    if (idx >= BB*TT*64) return;
    int i = idx & 63;
    int t = (idx >> 6) & (TT-1);
    int b = idx >> 15;

    int j = (i < 16) ? 0 : ((i < 40) ? 1 : 2);
    int pos = positions[(j*BB + b)*TT + t];

    double inv = exp2(((double)(-2*i) / 128.0) * 19.931568569324174);
    double ang = (double)pos * inv;
    double sd, cd;
    sincos(ang, &sd, &cd);
    float c = (float)cd, s = (float)sd;
    const float qs = 0.08838834764831845f;

    size_t qbase = ((size_t)(b*TT + t))*NQ*HH;
    #pragma unroll 4
    for (int n = 0; n < NQ; n++) {
        float x1 = g_q[qbase + n*HH + i];
        float x2 = g_q[qbase + n*HH + i + 64];
        g_q[qbase + n*HH + i]      = (x1*c - x2*s)*qs;
        g_q[qbase + n*HH + i + 64] = (x2*c + x1*s)*qs;
    }
    size_t kbase = ((size_t)(b*SEQ + SCACHE + t))*NKV*HH;
    #pragma unroll
    for (int kh = 0; kh < NKV; kh++) {
        float x1 = outk[kbase + kh*HH + i];
        float x2 = outk[kbase + kh*HH + i + 64];
        outk[kbase + kh*HH + i]      = x1*c - x2*s;
        outk[kbase + kh*HH + i + 64] = x2*c + x1*s;
    }
}

// ---------------------------------------------------------------------------
// Flash attention (scalar fp32)
// ---------------------------------------------------------------------------
#define QS_STRIDE 132
#define KC_STRIDE 132
#define VT_STRIDE 68
#define PS_STRIDE 68
#define ATTN_SMEM ((64*QS_STRIDE + 64*KC_STRIDE + 128*VT_STRIDE + 64*PS_STRIDE)*4)

__global__ __launch_bounds__(256) void attn_kernel(
    const float* __restrict__ kc, const float* __restrict__ vc)
{
    extern __shared__ __align__(16) float sm[];
    float* Qs = sm;
    float* Kc = Qs + 64*QS_STRIDE;
    float* Vt = Kc + 64*KC_STRIDE;
    float* Ps = Vt + 128*VT_STRIDE;

    int t0 = blockIdx.x * 64;
    int n  = blockIdx.y;
    int b  = blockIdx.z;
    int kh = n / GRP;
    int tid = threadIdx.x;
    int ty = tid >> 4, tx = tid & 15;

    for (int l = tid; l < 64*32; l += 256) {
        int r = l >> 5, h = (l & 31) * 4;
        *(float4*)&Qs[r*QS_STRIDE + h] =
            *(const float4*)&g_q[(((size_t)(b*TT + t0 + r))*NQ + n)*HH + h];
    }

    float m_i[4], l_i[4], acc[4][8];
    #pragma unroll
    for (int i = 0; i < 4; i++) {
        m_i[i] = -FLT_MAX; l_i[i] = 0.f;
        #pragma unroll
        for (int j = 0; j < 8; j++) acc[i][j] = 0.f;
    }

    int nchunks = (SCACHE + t0 + 64) >> 6;
    int vk = tid & 63, vh0 = (tid >> 6) * 32;

    for (int ch = 0; ch < nchunks; ch++) {
        int s0 = ch * 64;
        __syncthreads();
        for (int l = tid; l < 64*32; l += 256) {
            int c = l >> 5, h = (l & 31) * 4;
            *(float4*)&Kc[c*KC_STRIDE + h] =
                *(const float4*)&kc[(((size_t)(b*SEQ + s0 + c))*NKV + kh)*HH + h];
        }
        {
            const float* vrow = &vc[(((size_t)(b*SEQ + s0 + vk))*NKV + kh)*HH + vh0];
            #pragma unroll
            for (int qd = 0; qd < 8; qd++) {
                float4 vv = *(const float4*)(vrow + qd*4);
                Vt[(vh0 + qd*4 + 0)*VT_STRIDE + vk] = vv.x;
                Vt[(vh0 + qd*4 + 1)*VT_STRIDE + vk] = vv.y;
                Vt[(vh0 + qd*4 + 2)*VT_STRIDE + vk] = vv.z;
                Vt[(vh0 + qd*4 + 3)*VT_STRIDE + vk] = vv.w;
            }
        }
        __syncthreads();

        float sv[4][4];
        #pragma unroll
        for (int i = 0; i < 4; i++)
            #pragma unroll
            for (int jc = 0; jc < 4; jc++) sv[i][jc] = 0.f;
        #pragma unroll 4
        for (int h0 = 0; h0 < HH; h0 += 4) {
            float4 qv[4], kv[4];
            #pragma unroll
            for (int i = 0; i < 4; i++)
                qv[i] = *(const float4*)&Qs[(ty + 16*i)*QS_STRIDE + h0];
            #pragma unroll
            for (int jc = 0; jc < 4; jc++)
                kv[jc] = *(const float4*)&Kc[(tx + 16*jc)*KC_STRIDE + h0];
            #pragma unroll
            for (int i = 0; i < 4; i++)
                #pragma unroll
                for (int jc = 0; jc < 4; jc++)
                    sv[i][jc] += qv[i].x*kv[jc].x + qv[i].y*kv[jc].y
                               + qv[i].z*kv[jc].z + qv[i].w*kv[jc].w;
        }

        #pragma unroll
        for (int i = 0; i < 4; i++) {
            int smax = SCACHE + t0 + ty + 16*i;
            float mx = -FLT_MAX;
            #pragma unroll
            for (int jc = 0; jc < 4; jc++) {
                int s = s0 + tx + 16*jc;
                if (s > smax) sv[i][jc] = -FLT_MAX;
                mx = fmaxf(mx, sv[i][jc]);
            }
            mx = fmaxf(mx, __shfl_xor_sync(0xffffffffu, mx, 1));
            mx = fmaxf(mx, __shfl_xor_sync(0xffffffffu, mx, 2));
            mx = fmaxf(mx, __shfl_xor_sync(0xffffffffu, mx, 4));
            mx = fmaxf(mx, __shfl_xor_sync(0xffffffffu, mx, 8));
            float mnew = fmaxf(m_i[i], mx);
            float corr = __expf(m_i[i] - mnew);
            m_i[i] = mnew;
            float ps = 0.f;
            #pragma unroll
            for (int jc = 0; jc < 4; jc++) {
                float p = __expf(sv[i][jc] - mnew);
                Ps[(ty + 16*i)*PS_STRIDE + tx + 16*jc] = p;
                ps += p;
            }
            ps += __shfl_xor_sync(0xffffffffu, ps, 1);
            ps += __shfl_xor_sync(0xffffffffu, ps, 2);
            ps += __shfl_xor_sync(0xffffffffu, ps, 4);
            ps += __shfl_xor_sync(0xffffffffu, ps, 8);
            l_i[i] = l_i[i]*corr + ps;
            #pragma unroll
            for (int j = 0; j < 8; j++) acc[i][j] *= corr;
        }
        __syncthreads();

        #pragma unroll 4
        for (int k0 = 0; k0 < 64; k0 += 4) {
            float4 pv[4], vv[8];
            #pragma unroll
            for (int i = 0; i < 4; i++)
                pv[i] = *(const float4*)&Ps[(ty + 16*i)*PS_STRIDE + k0];
            #pragma unroll
            for (int j = 0; j < 8; j++)
                vv[j] = *(const float4*)&Vt[(tx + 16*j)*VT_STRIDE + k0];
            #pragma unroll
            for (int i = 0; i < 4; i++)
                #pragma unroll
                for (int j = 0; j < 8; j++)
                    acc[i][j] += pv[i].x*vv[j].x + pv[i].y*vv[j].y
                               + pv[i].z*vv[j].z + pv[i].w*vv[j].w;
        }
    }

    #pragma unroll
    for (int i = 0; i < 4; i++) {
        float inv = 1.f / l_i[i];
        int t = t0 + ty + 16*i;
        size_t base = (((size_t)(b*TT + t))*NQ + n)*HH;
        #pragma unroll
        for (int j = 0; j < 8; j++)
            g_enc[base + tx + 16*j] = acc[i][j]*inv;
    }
}

// ---------------------------------------------------------------------------
// Launch
// ---------------------------------------------------------------------------
extern "C" void kernel_launch(void* const* d_in, const int* in_sizes, int n_in,
                              void* d_out, int out_size)
{
    const float* x         = (const float*)d_in[0];
    const int*   positions = (const int*)d_in[1];
    const float* cache_k   = (const float*)d_in[3];
    const float* cache_v   = (const float*)d_in[4];
    const float* wq        = (const float*)d_in[5];
    const float* wk        = (const float*)d_in[6];
    const float* wv        = (const float*)d_in[7];
    const float* wo        = (const float*)d_in[8];

    float* out  = (float*)d_out;
    float* outk = out + (size_t)OUT_ELEMS;
    float* outv = outk + (size_t)KV_ELEMS;

    cudaFuncSetAttribute(attn_kernel, cudaFuncAttributeMaxDynamicSharedMemorySize, ATTN_SMEM);

    cache_copy_kernel<<<1024, 256>>>((const float4*)cache_k, (const float4*)cache_v,
                                     (float4*)outk, (float4*)outv);
    qkv_mma_kernel<<<dim3(8, 36), 256>>>(x, wq, wk, wv, outk, outv);
    rope_kernel<<<(BB*TT*64 + 255)/256, 256>>>(positions, outk);
    attn_kernel<<<dim3(TT/64, NQ, BB), 256, ATTN_SMEM>>>(outk, outv);
    out_mma_kernel<<<dim3(8, 28), 256>>>(wo, out);
}

// round 8
// speedup vs baseline: 3.2195x; 2.1389x over previous
#include <cuda_runtime.h>
#include <math.h>
#include <float.h>
#include <stdint.h>

// Problem constants
#define BB 2
#define TT 512
#define DM 3584
#define NQ 28
#define NKV 4
#define GRP 7
#define HH 128
#define SCACHE 3584
#define SEQ 4096

#define OUT_ELEMS (BB*TT*DM)
#define KV_ELEMS  (BB*SEQ*NKV*HH)

// Scratch
__device__ float g_q[BB*TT*NQ*HH];
__device__ float g_enc[BB*TT*NQ*HH];

__device__ __forceinline__ uint32_t f2tf32(float x) {
    uint32_t r;
    asm("cvt.rna.tf32.f32 %0, %1;" : "=r"(r) : "f"(x));
    return r;
}

__device__ __forceinline__ void mma_tf32(float c[4], const uint32_t a[4], const uint32_t b[2]) {
    asm volatile("mma.sync.aligned.m16n8k8.row.col.f32.tf32.tf32.f32 "
        "{%0,%1,%2,%3}, {%4,%5,%6,%7}, {%8,%9}, {%0,%1,%2,%3};"
        : "+f"(c[0]), "+f"(c[1]), "+f"(c[2]), "+f"(c[3])
        : "r"(a[0]), "r"(a[1]), "r"(a[2]), "r"(a[3]), "r"(b[0]), "r"(b[1]));
}

// ===========================================================================
// Dense GEMM mainloop (mma.sync tf32) — unchanged from round 6
// ===========================================================================
#define BK 32
#define SSTR 36
#define CHUNKS (DM/BK)

__device__ __forceinline__ void gemm_mma_mainloop(
    const float* __restrict__ Ag, int lda,
    const float* __restrict__ Bg, int ldb,
    float acc[2][8][4])
{
    __shared__ __align__(16) float As[128*SSTR];
    __shared__ __align__(16) float Bs[128*SSTR];
    const uint32_t* Au = (const uint32_t*)As;
    const uint32_t* Bu = (const uint32_t*)Bs;

    int tid = threadIdx.x;
    int wid = tid >> 5, lane = tid & 31;
    int wm = (wid & 3) * 32, wn = (wid >> 2) * 64;
    int g = lane >> 2, tg = lane & 3;

    #pragma unroll
    for (int mt = 0; mt < 2; mt++)
        #pragma unroll
        for (int nt = 0; nt < 8; nt++)
            #pragma unroll
            for (int q = 0; q < 4; q++) acc[mt][nt][q] = 0.f;

    float4 pa[4];
    float  pb[4][4];

    #pragma unroll
    for (int it = 0; it < 4; it++) {
        int idx = it * 256 + tid;
        int m = idx >> 3, kq = idx & 7;
        pa[it] = *(const float4*)(Ag + (size_t)m * lda + kq * 4);
        int n = idx & 127, kc0 = (idx >> 7) * 4;
        #pragma unroll
        for (int q = 0; q < 4; q++)
            pb[it][q] = Bg[(size_t)(kc0 + q) * ldb + n];
    }
    #pragma unroll
    for (int it = 0; it < 4; it++) {
        int idx = it * 256 + tid;
        int m = idx >> 3, kq = idx & 7;
        uint4 av;
        av.x = f2tf32(pa[it].x); av.y = f2tf32(pa[it].y);
        av.z = f2tf32(pa[it].z); av.w = f2tf32(pa[it].w);
        *(uint4*)&As[m * SSTR + kq * 4] = av;
        int n = idx & 127, kc0 = (idx >> 7) * 4;
        uint4 bv;
        bv.x = f2tf32(pb[it][0]); bv.y = f2tf32(pb[it][1]);
        bv.z = f2tf32(pb[it][2]); bv.w = f2tf32(pb[it][3]);
        *(uint4*)&Bs[n * SSTR + kc0] = bv;
    }
    __syncthreads();

    for (int c = 0; c < CHUNKS; c++) {
        if (c + 1 < CHUNKS) {
            int k0 = (c + 1) * BK;
            #pragma unroll
            for (int it = 0; it < 4; it++) {
                int idx = it * 256 + tid;
                int m = idx >> 3, kq = idx & 7;
                pa[it] = *(const float4*)(Ag + (size_t)m * lda + k0 + kq * 4);
                int n = idx & 127, kc0 = (idx >> 7) * 4;
                #pragma unroll
                for (int q = 0; q < 4; q++)
                    pb[it][q] = Bg[(size_t)(k0 + kc0 + q) * ldb + n];
            }
        }

        #pragma unroll
        for (int ks = 0; ks < 4; ks++) {
            int k = ks * 8;
            uint32_t af[2][4];
            #pragma unroll
            for (int mt = 0; mt < 2; mt++) {
                int r0 = (wm + mt * 16 + g) * SSTR;
                int r1 = (wm + mt * 16 + g + 8) * SSTR;
                af[mt][0] = Au[r0 + k + tg];
                af[mt][1] = Au[r1 + k + tg];
                af[mt][2] = Au[r0 + k + tg + 4];
                af[mt][3] = Au[r1 + k + tg + 4];
            }
            uint32_t bf[8][2];
            #pragma unroll
            for (int nt = 0; nt < 8; nt++) {
                int rb = (wn + nt * 8 + g) * SSTR;
                bf[nt][0] = Bu[rb + k + tg];
                bf[nt][1] = Bu[rb + k + tg + 4];
            }
            #pragma unroll
            for (int mt = 0; mt < 2; mt++)
                #pragma unroll
                for (int nt = 0; nt < 8; nt++)
                    mma_tf32(acc[mt][nt], af[mt], bf[nt]);
        }
        __syncthreads();

        if (c + 1 < CHUNKS) {
            #pragma unroll
            for (int it = 0; it < 4; it++) {
                int idx = it * 256 + tid;
                int m = idx >> 3, kq = idx & 7;
                uint4 av;
                av.x = f2tf32(pa[it].x); av.y = f2tf32(pa[it].y);
                av.z = f2tf32(pa[it].z); av.w = f2tf32(pa[it].w);
                *(uint4*)&As[m * SSTR + kq * 4] = av;
                int n = idx & 127, kc0 = (idx >> 7) * 4;
                uint4 bv;
                bv.x = f2tf32(pb[it][0]); bv.y = f2tf32(pb[it][1]);
                bv.z = f2tf32(pb[it][2]); bv.w = f2tf32(pb[it][3]);
                *(uint4*)&Bs[n * SSTR + kc0] = bv;
            }
            __syncthreads();
        }
    }
}

// ===========================================================================
// QKV projection
// ===========================================================================
__global__ __launch_bounds__(256, 2) void qkv_mma_kernel(
    const float* __restrict__ x,
    const float* __restrict__ wq, const float* __restrict__ wk,
    const float* __restrict__ wv,
    float* __restrict__ outk, float* __restrict__ outv)
{
    int m0 = blockIdx.x * 128;
    int hz = blockIdx.y;
    const float* Bg;
    if (hz < NQ)          Bg = wq + (size_t)hz * DM * HH;
    else if (hz < NQ+NKV) Bg = wk + (size_t)(hz - NQ) * DM * HH;
    else                  Bg = wv + (size_t)(hz - NQ - NKV) * DM * HH;

    float acc[2][8][4];
    gemm_mma_mainloop(x + (size_t)m0 * DM, DM, Bg, HH, acc);

    int tid = threadIdx.x;
    int wid = tid >> 5, lane = tid & 31;
    int wm = (wid & 3) * 32, wn = (wid >> 2) * 64;
    int g = lane >> 2, tg = lane & 3;

    #pragma unroll
    for (int mt = 0; mt < 2; mt++) {
        #pragma unroll
        for (int h2 = 0; h2 < 2; h2++) {
            int row = wm + mt * 16 + g + h2 * 8;
            int mg = m0 + row;
            int b = mg / TT, t = mg - b * TT;
            float* dst;
            if (hz < NQ)
                dst = g_q + ((size_t)mg * NQ + hz) * HH;
            else if (hz < NQ+NKV)
                dst = outk + (((size_t)(b * SEQ + SCACHE + t)) * NKV + (hz - NQ)) * HH;
            else
                dst = outv + (((size_t)(b * SEQ + SCACHE + t)) * NKV + (hz - NQ - NKV)) * HH;
            #pragma unroll
            for (int nt = 0; nt < 8; nt++) {
                float2 v = make_float2(acc[mt][nt][h2 * 2], acc[mt][nt][h2 * 2 + 1]);
                *(float2*)(dst + wn + nt * 8 + tg * 2) = v;
            }
        }
    }
}

// ===========================================================================
// Output projection
// ===========================================================================
__global__ __launch_bounds__(256, 2) void out_mma_kernel(
    const float* __restrict__ wo, float* __restrict__ out)
{
    int m0 = blockIdx.x * 128;
    int n0 = blockIdx.y * 128;

    float acc[2][8][4];
    gemm_mma_mainloop(g_enc + (size_t)m0 * DM, DM, wo + n0, DM, acc);

    int tid = threadIdx.x;
    int wid = tid >> 5, lane = tid & 31;
    int wm = (wid & 3) * 32, wn = (wid >> 2) * 64;
    int g = lane >> 2, tg = lane & 3;

    #pragma unroll
    for (int mt = 0; mt < 2; mt++) {
        #pragma unroll
        for (int h2 = 0; h2 < 2; h2++) {
            int row = wm + mt * 16 + g + h2 * 8;
            float* dst = out + (size_t)(m0 + row) * DM + n0;
            #pragma unroll
            for (int nt = 0; nt < 8; nt++) {
                float2 v = make_float2(acc[mt][nt][h2 * 2], acc[mt][nt][h2 * 2 + 1]);
                *(float2*)(dst + wn + nt * 8 + tg * 2) = v;
            }
        }
    }
}

// ---------------------------------------------------------------------------
// Cache copy
// ---------------------------------------------------------------------------
__global__ void cache_copy_kernel(const float4* __restrict__ ck,
                                  const float4* __restrict__ cv,
                                  float4* __restrict__ outk,
                                  float4* __restrict__ outv)
{
    const int per_b = SCACHE*NKV*HH/4;
    const int n4 = BB * per_b;
    for (int idx = blockIdx.x*blockDim.x + threadIdx.x; idx < n4;
         idx += gridDim.x*blockDim.x) {
        int b = idx / per_b;
        int r = idx - b*per_b;
        size_t o = (size_t)b*(SEQ*NKV*HH/4) + r;
        outk[o] = ck[idx];
        outv[o] = cv[idx];
    }
}

// ---------------------------------------------------------------------------
// mRoPE in place
// ---------------------------------------------------------------------------
__global__ void rope_kernel(const int* __restrict__ positions,
                            float* __restrict__ outk)
{
    int idx = blockIdx.x*blockDim.x + threadIdx.x;
    if (idx >= BB*TT*64) return;
    int i = idx & 63;
    int t = (idx >> 6) & (TT-1);
    int b = idx >> 15;

    int j = (i < 16) ? 0 : ((i < 40) ? 1 : 2);
    int pos = positions[(j*BB + b)*TT + t];

    double inv = exp2(((double)(-2*i) / 128.0) * 19.931568569324174);
    double ang = (double)pos * inv;
    double sd, cd;
    sincos(ang, &sd, &cd);
    float c = (float)cd, s = (float)sd;
    const float qs = 0.08838834764831845f;

    size_t qbase = ((size_t)(b*TT + t))*NQ*HH;
    #pragma unroll 4
    for (int n = 0; n < NQ; n++) {
        float x1 = g_q[qbase + n*HH + i];
        float x2 = g_q[qbase + n*HH + i + 64];
        g_q[qbase + n*HH + i]      = (x1*c - x2*s)*qs;
        g_q[qbase + n*HH + i + 64] = (x2*c + x1*s)*qs;
    }
    size_t kbase = ((size_t)(b*SEQ + SCACHE + t))*NKV*HH;
    #pragma unroll
    for (int kh = 0; kh < NKV; kh++) {
        float x1 = outk[kbase + kh*HH + i];
        float x2 = outk[kbase + kh*HH + i + 64];
        outk[kbase + kh*HH + i]      = x1*c - x2*s;
        outk[kbase + kh*HH + i + 64] = x2*c + x1*s;
    }
}

// ===========================================================================
// Flash attention via mma.sync tf32.
// CTA: 128 queries, one q-head, one batch. 8 warps, warp owns 16 rows.
// Chunks of 64 keys. Q fragments in registers; K/V tf32 in smem; P via smem.
// ===========================================================================
#define KC_STR 132
#define VT_STR 68
#define PS_STR 68
#define ATTN_SMEM ((64*KC_STR + 128*VT_STR + 128*PS_STR)*4)

__global__ __launch_bounds__(256, 1) void attn_mma_kernel(
    const float* __restrict__ kc, const float* __restrict__ vc)
{
    extern __shared__ __align__(16) float sm[];
    float* Kc = sm;                       // [64][KC_STR] tf32 bits
    float* Vt = Kc + 64*KC_STR;           // [128][VT_STR] tf32 bits (h-major)
    float* Ps = Vt + 128*VT_STR;          // [128][PS_STR] tf32 bits
    uint32_t* KcU = (uint32_t*)Kc;
    uint32_t* VtU = (uint32_t*)Vt;
    uint32_t* PsU = (uint32_t*)Ps;

    int t0 = blockIdx.x * 128;
    int n  = blockIdx.y;
    int b  = blockIdx.z;
    int kh = n / GRP;
    int tid = threadIdx.x, wid = tid >> 5, lane = tid & 31;
    int g = lane >> 2, tg = lane & 3;
    int wm = wid * 16;
    int r0 = wm + g, r1 = r0 + 8;          // this thread's two query rows (local)

    // Q fragments (roped+scaled already): qa[ks][0..3]
    uint32_t qa[16][4];
    {
        const float* q0 = g_q + (((size_t)(b*TT + t0 + r0))*NQ + n)*HH;
        const float* q1 = g_q + (((size_t)(b*TT + t0 + r1))*NQ + n)*HH;
        #pragma unroll
        for (int ks = 0; ks < 16; ks++) {
            qa[ks][0] = f2tf32(q0[ks*8 + tg]);
            qa[ks][1] = f2tf32(q1[ks*8 + tg]);
            qa[ks][2] = f2tf32(q0[ks*8 + tg + 4]);
            qa[ks][3] = f2tf32(q1[ks*8 + tg + 4]);
        }
    }

    float oacc[16][4];
    #pragma unroll
    for (int nt = 0; nt < 16; nt++)
        #pragma unroll
        for (int q = 0; q < 4; q++) oacc[nt][q] = 0.f;
    float mrow[2] = {-FLT_MAX, -FLT_MAX};
    float lrow[2] = {0.f, 0.f};

    int nchunks = (SCACHE + t0 + 128) >> 6;
    int first_masked = (SCACHE + t0) >> 6;
    int vk = tid & 63, vh0 = (tid >> 6) * 32;

    for (int ch = 0; ch < nchunks; ch++) {
        int s0 = ch * 64;
        __syncthreads();   // prior PV reads of Vt done
        // K chunk [64][128] -> Kc (tf32), key-major
        #pragma unroll
        for (int it = 0; it < 8; it++) {
            int idx = it * 256 + tid;
            int row = idx >> 5, col = (idx & 31) * 4;
            float4 v = *(const float4*)&kc[(((size_t)(b*SEQ + s0 + row))*NKV + kh)*HH + col];
            uint4 o;
            o.x = f2tf32(v.x); o.y = f2tf32(v.y); o.z = f2tf32(v.z); o.w = f2tf32(v.w);
            *(uint4*)&KcU[row*KC_STR + col] = o;
        }
        // V chunk transposed -> Vt[h][key] (tf32)
        {
            const float* vrow = &vc[(((size_t)(b*SEQ + s0 + vk))*NKV + kh)*HH + vh0];
            #pragma unroll
            for (int qd = 0; qd < 8; qd++) {
                float4 vv = *(const float4*)(vrow + qd*4);
                VtU[(vh0 + qd*4 + 0)*VT_STR + vk] = f2tf32(vv.x);
                VtU[(vh0 + qd*4 + 1)*VT_STR + vk] = f2tf32(vv.y);
                VtU[(vh0 + qd*4 + 2)*VT_STR + vk] = f2tf32(vv.z);
                VtU[(vh0 + qd*4 + 3)*VT_STR + vk] = f2tf32(vv.w);
            }
        }
        __syncthreads();

        // ---- S = Q K^T : warp computes 16x64 ----
        float sacc[8][4];
        #pragma unroll
        for (int nt = 0; nt < 8; nt++)
            #pragma unroll
            for (int q = 0; q < 4; q++) sacc[nt][q] = 0.f;

        #pragma unroll
        for (int ks = 0; ks < 16; ks++) {
            uint32_t bf[8][2];
            #pragma unroll
            for (int nt = 0; nt < 8; nt++) {
                int rb = (nt*8 + g)*KC_STR + ks*8 + tg;
                bf[nt][0] = KcU[rb];
                bf[nt][1] = KcU[rb + 4];
            }
            #pragma unroll
            for (int nt = 0; nt < 8; nt++)
                mma_tf32(sacc[nt], qa[ks], bf[nt]);
        }

        // ---- causal mask (only last 2 chunks) ----
        if (ch >= first_masked) {
            int smax0 = SCACHE + t0 + r0;
            int smax1 = SCACHE + t0 + r1;
            #pragma unroll
            for (int nt = 0; nt < 8; nt++) {
                int col = s0 + nt*8 + 2*tg;
                if (col     > smax0) sacc[nt][0] = -FLT_MAX;
                if (col + 1 > smax0) sacc[nt][1] = -FLT_MAX;
                if (col     > smax1) sacc[nt][2] = -FLT_MAX;
                if (col + 1 > smax1) sacc[nt][3] = -FLT_MAX;
            }
        }

        // ---- online softmax per row (rows are warp-private) ----
        #pragma unroll
        for (int hr = 0; hr < 2; hr++) {
            float mx = -FLT_MAX;
            #pragma unroll
            for (int nt = 0; nt < 8; nt++)
                mx = fmaxf(mx, fmaxf(sacc[nt][hr*2], sacc[nt][hr*2+1]));
            mx = fmaxf(mx, __shfl_xor_sync(0xffffffffu, mx, 1));
            mx = fmaxf(mx, __shfl_xor_sync(0xffffffffu, mx, 2));
            float mnew = fmaxf(mrow[hr], mx);
            float corr = __expf(mrow[hr] - mnew);
            mrow[hr] = mnew;
            int prow = hr ? r1 : r0;
            float rs = 0.f;
            #pragma unroll
            for (int nt = 0; nt < 8; nt++) {
                float p0 = __expf(sacc[nt][hr*2]   - mnew);
                float p1 = __expf(sacc[nt][hr*2+1] - mnew);
                rs += p0 + p1;
                uint2 pp;
                pp.x = f2tf32(p0); pp.y = f2tf32(p1);
                *(uint2*)&PsU[prow*PS_STR + nt*8 + 2*tg] = pp;
            }
            rs += __shfl_xor_sync(0xffffffffu, rs, 1);
            rs += __shfl_xor_sync(0xffffffffu, rs, 2);
            lrow[hr] = lrow[hr]*corr + rs;
            #pragma unroll
            for (int nt = 0; nt < 16; nt++) {
                oacc[nt][hr*2]   *= corr;
                oacc[nt][hr*2+1] *= corr;
            }
        }
        __syncwarp();   // P rows are warp-private: make STS visible to warp

        // ---- O += P V : warp computes 16x128 ----
        #pragma unroll
        for (int k2 = 0; k2 < 8; k2++) {
            int k = k2 * 8;
            uint32_t pa[4];
            pa[0] = PsU[r0*PS_STR + k + tg];
            pa[1] = PsU[r1*PS_STR + k + tg];
            pa[2] = PsU[r0*PS_STR + k + tg + 4];
            pa[3] = PsU[r1*PS_STR + k + tg + 4];
            #pragma unroll
            for (int nt = 0; nt < 16; nt++) {
                int rb = (nt*8 + g)*VT_STR + k + tg;
                uint32_t vb[2];
                vb[0] = VtU[rb];
                vb[1] = VtU[rb + 4];
                mma_tf32(oacc[nt], pa, vb);
            }
        }
    }

    // ---- finalize ----
    float inv0 = 1.f / lrow[0];
    float inv1 = 1.f / lrow[1];
    float* e0 = g_enc + (((size_t)(b*TT + t0 + r0))*NQ + n)*HH;
    float* e1 = g_enc + (((size_t)(b*TT + t0 + r1))*NQ + n)*HH;
    #pragma unroll
    for (int nt = 0; nt < 16; nt++) {
        int col = nt*8 + 2*tg;
        *(float2*)(e0 + col) = make_float2(oacc[nt][0]*inv0, oacc[nt][1]*inv0);
        *(float2*)(e1 + col) = make_float2(oacc[nt][2]*inv1, oacc[nt][3]*inv1);
    }
}

// ---------------------------------------------------------------------------
// Launch
// ---------------------------------------------------------------------------
extern "C" void kernel_launch(void* const* d_in, const int* in_sizes, int n_in,
                              void* d_out, int out_size)
{
    const float* x         = (const float*)d_in[0];
    const int*   positions = (const int*)d_in[1];
    const float* cache_k   = (const float*)d_in[3];
    const float* cache_v   = (const float*)d_in[4];
    const float* wq        = (const float*)d_in[5];
    const float* wk        = (const float*)d_in[6];
    const float* wv        = (const float*)d_in[7];
    const float* wo        = (const float*)d_in[8];

    float* out  = (float*)d_out;
    float* outk = out + (size_t)OUT_ELEMS;
    float* outv = outk + (size_t)KV_ELEMS;

    cudaFuncSetAttribute(attn_mma_kernel, cudaFuncAttributeMaxDynamicSharedMemorySize, ATTN_SMEM);

    cache_copy_kernel<<<1024, 256>>>((const float4*)cache_k, (const float4*)cache_v,
                                     (float4*)outk, (float4*)outv);
    qkv_mma_kernel<<<dim3(8, 36), 256>>>(x, wq, wk, wv, outk, outv);
    rope_kernel<<<(BB*TT*64 + 255)/256, 256>>>(positions, outk);
    attn_mma_kernel<<<dim3(TT/128, NQ, BB), 256, ATTN_SMEM>>>(outk, outv);
    out_mma_kernel<<<dim3(8, 28), 256>>>(wo, out);
}

// round 9
// speedup vs baseline: 4.0983x; 1.2730x over previous
#include <cuda_runtime.h>
#include <cuda_fp16.h>
#include <math.h>
#include <float.h>
#include <stdint.h>

// Problem constants
#define BB 2
#define TT 512
#define DM 3584
#define NQ 28
#define NKV 4
#define GRP 7
#define HH 128
#define SCACHE 3584
#define SEQ 4096

#define OUT_ELEMS (BB*TT*DM)
#define KV_ELEMS  (BB*SEQ*NKV*HH)

// Scratch
__device__ float g_q[BB*TT*NQ*HH];
__device__ float g_enc[BB*TT*NQ*HH];

__device__ __forceinline__ uint32_t f2tf32(float x) {
    uint32_t r;
    asm("cvt.rna.tf32.f32 %0, %1;" : "=r"(r) : "f"(x));
    return r;
}

__device__ __forceinline__ void mma_tf32(float c[4], const uint32_t a[4], const uint32_t b[2]) {
    asm volatile("mma.sync.aligned.m16n8k8.row.col.f32.tf32.tf32.f32 "
        "{%0,%1,%2,%3}, {%4,%5,%6,%7}, {%8,%9}, {%0,%1,%2,%3};"
        : "+f"(c[0]), "+f"(c[1]), "+f"(c[2]), "+f"(c[3])
        : "r"(a[0]), "r"(a[1]), "r"(a[2]), "r"(a[3]), "r"(b[0]), "r"(b[1]));
}

__device__ __forceinline__ void mma_f16(float c[4], const uint32_t a[4], const uint32_t b[2]) {
    asm volatile("mma.sync.aligned.m16n8k16.row.col.f32.f16.f16.f32 "
        "{%0,%1,%2,%3}, {%4,%5,%6,%7}, {%8,%9}, {%0,%1,%2,%3};"
        : "+f"(c[0]), "+f"(c[1]), "+f"(c[2]), "+f"(c[3])
        : "r"(a[0]), "r"(a[1]), "r"(a[2]), "r"(a[3]), "r"(b[0]), "r"(b[1]));
}

__device__ __forceinline__ void ldsm4(uint32_t& r0, uint32_t& r1, uint32_t& r2, uint32_t& r3,
                                      uint32_t addr) {
    asm volatile("ldmatrix.sync.aligned.m8n8.x4.shared.b16 {%0,%1,%2,%3}, [%4];"
        : "=r"(r0), "=r"(r1), "=r"(r2), "=r"(r3) : "r"(addr));
}

__device__ __forceinline__ uint32_t smem_u32(const void* p) {
    uint32_t a;
    asm("{ .reg .u64 t; cvta.to.shared.u64 t, %1; cvt.u32.u64 %0, t; }" : "=r"(a) : "l"(p));
    return a;
}

__device__ __forceinline__ uint32_t pack_h2(float a, float b) {
    __half2 h = __floats2half2_rn(a, b);
    return *(uint32_t*)&h;
}

// ===========================================================================
// Dense GEMM mainloop (mma.sync tf32) — unchanged (verified)
// ===========================================================================
#define BK 32
#define SSTR 36
#define CHUNKS (DM/BK)

__device__ __forceinline__ void gemm_mma_mainloop(
    const float* __restrict__ Ag, int lda,
    const float* __restrict__ Bg, int ldb,
    float acc[2][8][4])
{
    __shared__ __align__(16) float As[128*SSTR];
    __shared__ __align__(16) float Bs[128*SSTR];
    const uint32_t* Au = (const uint32_t*)As;
    const uint32_t* Bu = (const uint32_t*)Bs;

    int tid = threadIdx.x;
    int wid = tid >> 5, lane = tid & 31;
    int wm = (wid & 3) * 32, wn = (wid >> 2) * 64;
    int g = lane >> 2, tg = lane & 3;

    #pragma unroll
    for (int mt = 0; mt < 2; mt++)
        #pragma unroll
        for (int nt = 0; nt < 8; nt++)
            #pragma unroll
            for (int q = 0; q < 4; q++) acc[mt][nt][q] = 0.f;

    float4 pa[4];
    float  pb[4][4];

    #pragma unroll
    for (int it = 0; it < 4; it++) {
        int idx = it * 256 + tid;
        int m = idx >> 3, kq = idx & 7;
        pa[it] = *(const float4*)(Ag + (size_t)m * lda + kq * 4);
        int n = idx & 127, kc0 = (idx >> 7) * 4;
        #pragma unroll
        for (int q = 0; q < 4; q++)
            pb[it][q] = Bg[(size_t)(kc0 + q) * ldb + n];
    }
    #pragma unroll
    for (int it = 0; it < 4; it++) {
        int idx = it * 256 + tid;
        int m = idx >> 3, kq = idx & 7;
        uint4 av;
        av.x = f2tf32(pa[it].x); av.y = f2tf32(pa[it].y);
        av.z = f2tf32(pa[it].z); av.w = f2tf32(pa[it].w);
        *(uint4*)&As[m * SSTR + kq * 4] = av;
        int n = idx & 127, kc0 = (idx >> 7) * 4;
        uint4 bv;
        bv.x = f2tf32(pb[it][0]); bv.y = f2tf32(pb[it][1]);
        bv.z = f2tf32(pb[it][2]); bv.w = f2tf32(pb[it][3]);
        *(uint4*)&Bs[n * SSTR + kc0] = bv;
    }
    __syncthreads();

    for (int c = 0; c < CHUNKS; c++) {
        if (c + 1 < CHUNKS) {
            int k0 = (c + 1) * BK;
            #pragma unroll
            for (int it = 0; it < 4; it++) {
                int idx = it * 256 + tid;
                int m = idx >> 3, kq = idx & 7;
                pa[it] = *(const float4*)(Ag + (size_t)m * lda + k0 + kq * 4);
                int n = idx & 127, kc0 = (idx >> 7) * 4;
                #pragma unroll
                for (int q = 0; q < 4; q++)
                    pb[it][q] = Bg[(size_t)(k0 + kc0 + q) * ldb + n];
            }
        }

        #pragma unroll
        for (int ks = 0; ks < 4; ks++) {
            int k = ks * 8;
            uint32_t af[2][4];
            #pragma unroll
            for (int mt = 0; mt < 2; mt++) {
                int r0 = (wm + mt * 16 + g) * SSTR;
                int r1 = (wm + mt * 16 + g + 8) * SSTR;
                af[mt][0] = Au[r0 + k + tg];
                af[mt][1] = Au[r1 + k + tg];
                af[mt][2] = Au[r0 + k + tg + 4];
                af[mt][3] = Au[r1 + k + tg + 4];
            }
            uint32_t bf[8][2];
            #pragma unroll
            for (int nt = 0; nt < 8; nt++) {
                int rb = (wn + nt * 8 + g) * SSTR;
                bf[nt][0] = Bu[rb + k + tg];
                bf[nt][1] = Bu[rb + k + tg + 4];
            }
            #pragma unroll
            for (int mt = 0; mt < 2; mt++)
                #pragma unroll
                for (int nt = 0; nt < 8; nt++)
                    mma_tf32(acc[mt][nt], af[mt], bf[nt]);
        }
        __syncthreads();

        if (c + 1 < CHUNKS) {
            #pragma unroll
            for (int it = 0; it < 4; it++) {
                int idx = it * 256 + tid;
                int m = idx >> 3, kq = idx & 7;
                uint4 av;
                av.x = f2tf32(pa[it].x); av.y = f2tf32(pa[it].y);
                av.z = f2tf32(pa[it].z); av.w = f2tf32(pa[it].w);
                *(uint4*)&As[m * SSTR + kq * 4] = av;
                int n = idx & 127, kc0 = (idx >> 7) * 4;
                uint4 bv;
                bv.x = f2tf32(pb[it][0]); bv.y = f2tf32(pb[it][1]);
                bv.z = f2tf32(pb[it][2]); bv.w = f2tf32(pb[it][3]);
                *(uint4*)&Bs[n * SSTR + kc0] = bv;
            }
            __syncthreads();
        }
    }
}

// ===========================================================================
// QKV projection
// ===========================================================================
__global__ __launch_bounds__(256, 2) void qkv_mma_kernel(
    const float* __restrict__ x,
    const float* __restrict__ wq, const float* __restrict__ wk,
    const float* __restrict__ wv,
    float* __restrict__ outk, float* __restrict__ outv)
{
    int m0 = blockIdx.x * 128;
    int hz = blockIdx.y;
    const float* Bg;
    if (hz < NQ)          Bg = wq + (size_t)hz * DM * HH;
    else if (hz < NQ+NKV) Bg = wk + (size_t)(hz - NQ) * DM * HH;
    else                  Bg = wv + (size_t)(hz - NQ - NKV) * DM * HH;

    float acc[2][8][4];
    gemm_mma_mainloop(x + (size_t)m0 * DM, DM, Bg, HH, acc);

    int tid = threadIdx.x;
    int wid = tid >> 5, lane = tid & 31;
    int wm = (wid & 3) * 32, wn = (wid >> 2) * 64;
    int g = lane >> 2, tg = lane & 3;

    #pragma unroll
    for (int mt = 0; mt < 2; mt++) {
        #pragma unroll
        for (int h2 = 0; h2 < 2; h2++) {
            int row = wm + mt * 16 + g + h2 * 8;
            int mg = m0 + row;
            int b = mg / TT, t = mg - b * TT;
            float* dst;
            if (hz < NQ)
                dst = g_q + ((size_t)mg * NQ + hz) * HH;
            else if (hz < NQ+NKV)
                dst = outk + (((size_t)(b * SEQ + SCACHE + t)) * NKV + (hz - NQ)) * HH;
            else
                dst = outv + (((size_t)(b * SEQ + SCACHE + t)) * NKV + (hz - NQ - NKV)) * HH;
            #pragma unroll
            for (int nt = 0; nt < 8; nt++) {
                float2 v = make_float2(acc[mt][nt][h2 * 2], acc[mt][nt][h2 * 2 + 1]);
                *(float2*)(dst + wn + nt * 8 + tg * 2) = v;
            }
        }
    }
}

// ===========================================================================
// Output projection
// ===========================================================================
__global__ __launch_bounds__(256, 2) void out_mma_kernel(
    const float* __restrict__ wo, float* __restrict__ out)
{
    int m0 = blockIdx.x * 128;
    int n0 = blockIdx.y * 128;

    float acc[2][8][4];
    gemm_mma_mainloop(g_enc + (size_t)m0 * DM, DM, wo + n0, DM, acc);

    int tid = threadIdx.x;
    int wid = tid >> 5, lane = tid & 31;
    int wm = (wid & 3) * 32, wn = (wid >> 2) * 64;
    int g = lane >> 2, tg = lane & 3;

    #pragma unroll
    for (int mt = 0; mt < 2; mt++) {
        #pragma unroll
        for (int h2 = 0; h2 < 2; h2++) {
            int row = wm + mt * 16 + g + h2 * 8;
            float* dst = out + (size_t)(m0 + row) * DM + n0;
            #pragma unroll
            for (int nt = 0; nt < 8; nt++) {
                float2 v = make_float2(acc[mt][nt][h2 * 2], acc[mt][nt][h2 * 2 + 1]);
                *(float2*)(dst + wn + nt * 8 + tg * 2) = v;
            }
        }
    }
}

// ---------------------------------------------------------------------------
// Cache copy
// ---------------------------------------------------------------------------
__global__ void cache_copy_kernel(const float4* __restrict__ ck,
                                  const float4* __restrict__ cv,
                                  float4* __restrict__ outk,
                                  float4* __restrict__ outv)
{
    const int per_b = SCACHE*NKV*HH/4;
    const int n4 = BB * per_b;
    for (int idx = blockIdx.x*blockDim.x + threadIdx.x; idx < n4;
         idx += gridDim.x*blockDim.x) {
        int b = idx / per_b;
        int r = idx - b*per_b;
        size_t o = (size_t)b*(SEQ*NKV*HH/4) + r;
        outk[o] = ck[idx];
        outv[o] = cv[idx];
    }
}

// ---------------------------------------------------------------------------
// mRoPE in place
// ---------------------------------------------------------------------------
__global__ void rope_kernel(const int* __restrict__ positions,
                            float* __restrict__ outk)
{
    int idx = blockIdx.x*blockDim.x + threadIdx.x;
    if (idx >= BB*TT*64) return;
    int i = idx & 63;
    int t = (idx >> 6) & (TT-1);
    int b = idx >> 15;

    int j = (i < 16) ? 0 : ((i < 40) ? 1 : 2);
    int pos = positions[(j*BB + b)*TT + t];

    double inv = exp2(((double)(-2*i) / 128.0) * 19.931568569324174);
    double ang = (double)pos * inv;
    double sd, cd;
    sincos(ang, &sd, &cd);
    float c = (float)cd, s = (float)sd;
    const float qs = 0.08838834764831845f;

    size_t qbase = ((size_t)(b*TT + t))*NQ*HH;
    #pragma unroll 4
    for (int n = 0; n < NQ; n++) {
        float x1 = g_q[qbase + n*HH + i];
        float x2 = g_q[qbase + n*HH + i + 64];
        g_q[qbase + n*HH + i]      = (x1*c - x2*s)*qs;
        g_q[qbase + n*HH + i + 64] = (x2*c + x1*s)*qs;
    }
    size_t kbase = ((size_t)(b*SEQ + SCACHE + t))*NKV*HH;
    #pragma unroll
    for (int kh = 0; kh < NKV; kh++) {
        float x1 = outk[kbase + kh*HH + i];
        float x2 = outk[kbase + kh*HH + i + 64];
        outk[kbase + kh*HH + i]      = x1*c - x2*s;
        outk[kbase + kh*HH + i + 64] = x2*c + x1*s;
    }
}

// ===========================================================================
// Flash attention: fp16 operands + ldmatrix + m16n8k16, fp32 softmax/accum.
// CTA: 64 queries x 1 head x 1 batch; 4 warps, warp owns 16 query rows.
// Chunks of 64 keys. 3 CTAs/SM (static smem 44KB, regs capped).
// ===========================================================================
#define KS2 136     // K row stride in halves (128+8): 272B rows, odd x16B
#define VS2 72      // Vt row stride (64+8): 144B
#define PSH 72      // P row stride: 144B

__global__ __launch_bounds__(128, 3) void attn_f16_kernel(
    const float* __restrict__ kc, const float* __restrict__ vc)
{
    __shared__ __align__(16) __half Kc[64*KS2];
    __shared__ __align__(16) __half Vt[128*VS2];
    __shared__ __align__(16) __half Ps[64*PSH];

    int t0 = blockIdx.x * 64;
    int n  = blockIdx.y;
    int b  = blockIdx.z;
    int kh = n / GRP;
    int tid = threadIdx.x, wid = tid >> 5, lane = tid & 31;
    int g = lane >> 2, tg = lane & 3;
    int wm = wid * 16;
    int r0 = wm + g, r1 = r0 + 8;

    uint32_t kc_b = smem_u32(Kc), vt_b = smem_u32(Vt), ps_b = smem_u32(Ps);

    // ldmatrix per-lane address bases
    int keyoff = (lane & 7) + ((lane >> 4) & 1) * 8;
    int hoff   = ((lane >> 3) & 1) * 8;
    uint32_t kaddr = kc_b + (uint32_t)(keyoff * KS2 + hoff) * 2;      // + (kb*16*KS2 + ks*16)*2

    int prow_l = wm + (lane & 7) + ((lane >> 3) & 1) * 8;
    int pcol_l = ((lane >> 4) & 1) * 8;
    uint32_t paddr = ps_b + (uint32_t)(prow_l * PSH + pcol_l) * 2;    // + kk*32

    int vrow_l = (lane & 7) + ((lane >> 4) & 1) * 8;
    int vcol_l = ((lane >> 3) & 1) * 8;
    uint32_t vaddr = vt_b + (uint32_t)(vrow_l * VS2 + vcol_l) * 2;    // + (nb*16*VS2 + kk*16)*2

    // Q fragments (fp16 packed), built once from gmem
    uint32_t qa[8][4];
    {
        const float* q0 = g_q + (((size_t)(b*TT + t0 + r0))*NQ + n)*HH;
        const float* q1 = g_q + (((size_t)(b*TT + t0 + r1))*NQ + n)*HH;
        #pragma unroll
        for (int ks = 0; ks < 8; ks++) {
            float2 v0 = *(const float2*)(q0 + ks*16 + 2*tg);
            float2 v1 = *(const float2*)(q1 + ks*16 + 2*tg);
            float2 v2 = *(const float2*)(q0 + ks*16 + 2*tg + 8);
            float2 v3 = *(const float2*)(q1 + ks*16 + 2*tg + 8);
            qa[ks][0] = pack_h2(v0.x, v0.y);
            qa[ks][1] = pack_h2(v1.x, v1.y);
            qa[ks][2] = pack_h2(v2.x, v2.y);
            qa[ks][3] = pack_h2(v3.x, v3.y);
        }
    }

    float oacc[16][4];
    #pragma unroll
    for (int nt = 0; nt < 16; nt++)
        #pragma unroll
        for (int q = 0; q < 4; q++) oacc[nt][q] = 0.f;
    float mrow[2] = {-FLT_MAX, -FLT_MAX};
    float lrow[2] = {0.f, 0.f};

    int nchunks = (SCACHE + t0 + 64) >> 6;
    int vk2 = (tid & 31) * 2, vh0 = (tid >> 5) * 32;

    for (int ch = 0; ch < nchunks; ch++) {
        int s0 = ch * 64;
        __syncthreads();   // prior chunk's smem reads done

        // ---- K chunk [64 keys][128 h] -> fp16 ----
        #pragma unroll
        for (int it = 0; it < 16; it++) {
            int idx = it * 128 + tid;
            int row = idx >> 5, col4 = (idx & 31) * 4;
            float4 v = *(const float4*)&kc[(((size_t)(b*SEQ + s0 + row))*NKV + kh)*HH + col4];
            uint2 o;
            o.x = pack_h2(v.x, v.y);
            o.y = pack_h2(v.z, v.w);
            *(uint2*)&Kc[row * KS2 + col4] = o;
        }
        // ---- V chunk transposed -> Vt[h][key] fp16 (2 keys per thread) ----
        {
            const float* vr0 = &vc[(((size_t)(b*SEQ + s0 + vk2))*NKV + kh)*HH + vh0];
            const float* vr1 = vr0 + NKV*HH;
            #pragma unroll
            for (int qd = 0; qd < 8; qd++) {
                float4 a = *(const float4*)(vr0 + qd*4);
                float4 c2 = *(const float4*)(vr1 + qd*4);
                *(uint32_t*)&Vt[(vh0 + qd*4 + 0)*VS2 + vk2] = pack_h2(a.x, c2.x);
                *(uint32_t*)&Vt[(vh0 + qd*4 + 1)*VS2 + vk2] = pack_h2(a.y, c2.y);
                *(uint32_t*)&Vt[(vh0 + qd*4 + 2)*VS2 + vk2] = pack_h2(a.z, c2.z);
                *(uint32_t*)&Vt[(vh0 + qd*4 + 3)*VS2 + vk2] = pack_h2(a.w, c2.w);
            }
        }
        __syncthreads();

        // ---- S = Q K^T : warp computes 16x64 ----
        float sacc[8][4];
        #pragma unroll
        for (int nt = 0; nt < 8; nt++)
            #pragma unroll
            for (int q = 0; q < 4; q++) sacc[nt][q] = 0.f;

        #pragma unroll
        for (int ks = 0; ks < 8; ks++) {
            #pragma unroll
            for (int kb = 0; kb < 4; kb++) {
                uint32_t b0, b1, b2, b3;
                ldsm4(b0, b1, b2, b3, kaddr + (uint32_t)(kb*16*KS2 + ks*16)*2);
                uint32_t lo[2] = {b0, b1}, hi[2] = {b2, b3};
                mma_f16(sacc[2*kb],   qa[ks], lo);
                mma_f16(sacc[2*kb+1], qa[ks], hi);
            }
        }

        // ---- causal mask (only the final chunk) ----
        if (ch == nchunks - 1) {
            int smax0 = SCACHE + t0 + r0;
            int smax1 = SCACHE + t0 + r1;
            #pragma unroll
            for (int nt = 0; nt < 8; nt++) {
                int col = s0 + nt*8 + 2*tg;
                if (col     > smax0) sacc[nt][0] = -FLT_MAX;
                if (col + 1 > smax0) sacc[nt][1] = -FLT_MAX;
                if (col     > smax1) sacc[nt][2] = -FLT_MAX;
                if (col + 1 > smax1) sacc[nt][3] = -FLT_MAX;
            }
        }

        // ---- online softmax (rows warp-private), P -> fp16 smem ----
        #pragma unroll
        for (int hr = 0; hr < 2; hr++) {
            float mx = -FLT_MAX;
            #pragma unroll
            for (int nt = 0; nt < 8; nt++)
                mx = fmaxf(mx, fmaxf(sacc[nt][hr*2], sacc[nt][hr*2+1]));
            mx = fmaxf(mx, __shfl_xor_sync(0xffffffffu, mx, 1));
            mx = fmaxf(mx, __shfl_xor_sync(0xffffffffu, mx, 2));
            float mnew = fmaxf(mrow[hr], mx);
            float corr = __expf(mrow[hr] - mnew);
            mrow[hr] = mnew;
            int prow = hr ? r1 : r0;
            float rs = 0.f;
            #pragma unroll
            for (int nt = 0; nt < 8; nt++) {
                float p0 = __expf(sacc[nt][hr*2]   - mnew);
                float p1 = __expf(sacc[nt][hr*2+1] - mnew);
                rs += p0 + p1;
                *(uint32_t*)&Ps[prow*PSH + nt*8 + 2*tg] = pack_h2(p0, p1);
            }
            rs += __shfl_xor_sync(0xffffffffu, rs, 1);
            rs += __shfl_xor_sync(0xffffffffu, rs, 2);
            lrow[hr] = lrow[hr]*corr + rs;
            #pragma unroll
            for (int nt = 0; nt < 16; nt++) {
                oacc[nt][hr*2]   *= corr;
                oacc[nt][hr*2+1] *= corr;
            }
        }
        __syncwarp();   // P rows warp-private: order STS before ldmatrix

        // ---- O += P V : warp computes 16x128 ----
        #pragma unroll
        for (int kk = 0; kk < 4; kk++) {
            uint32_t pa[4];
            ldsm4(pa[0], pa[1], pa[2], pa[3], paddr + (uint32_t)(kk*16)*2);
            #pragma unroll
            for (int nb = 0; nb < 8; nb++) {
                uint32_t v0, v1, v2, v3;
                ldsm4(v0, v1, v2, v3, vaddr + (uint32_t)(nb*16*VS2 + kk*16)*2);
                uint32_t lo[2] = {v0, v1}, hi[2] = {v2, v3};
                mma_f16(oacc[2*nb],   pa, lo);
                mma_f16(oacc[2*nb+1], pa, hi);
            }
        }
    }

    // ---- finalize ----
    float inv0 = 1.f / lrow[0];
    float inv1 = 1.f / lrow[1];
    float* e0 = g_enc + (((size_t)(b*TT + t0 + r0))*NQ + n)*HH;
    float* e1 = g_enc + (((size_t)(b*TT + t0 + r1))*NQ + n)*HH;
    #pragma unroll
    for (int nt = 0; nt < 16; nt++) {
        int col = nt*8 + 2*tg;
        *(float2*)(e0 + col) = make_float2(oacc[nt][0]*inv0, oacc[nt][1]*inv0);
        *(float2*)(e1 + col) = make_float2(oacc[nt][2]*inv1, oacc[nt][3]*inv1);
    }
}

// ---------------------------------------------------------------------------
// Launch
// ---------------------------------------------------------------------------
extern "C" void kernel_launch(void* const* d_in, const int* in_sizes, int n_in,
                              void* d_out, int out_size)
{
    const float* x         = (const float*)d_in[0];
    const int*   positions = (const int*)d_in[1];
    const float* cache_k   = (const float*)d_in[3];
    const float* cache_v   = (const float*)d_in[4];
    const float* wq        = (const float*)d_in[5];
    const float* wk        = (const float*)d_in[6];
    const float* wv        = (const float*)d_in[7];
    const float* wo        = (const float*)d_in[8];

    float* out  = (float*)d_out;
    float* outk = out + (size_t)OUT_ELEMS;
    float* outv = outk + (size_t)KV_ELEMS;

    cache_copy_kernel<<<1024, 256>>>((const float4*)cache_k, (const float4*)cache_v,
                                     (float4*)outk, (float4*)outv);
    qkv_mma_kernel<<<dim3(8, 36), 256>>>(x, wq, wk, wv, outk, outv);
    rope_kernel<<<(BB*TT*64 + 255)/256, 256>>>(positions, outk);
    attn_f16_kernel<<<dim3(TT/64, NQ, BB), 128>>>(outk, outv);
    out_mma_kernel<<<dim3(8, 28), 256>>>(wo, out);
}

// round 11
// speedup vs baseline: 7.2413x; 1.7669x over previous
#include <cuda_runtime.h>
#include <cuda_fp16.h>
#include <math.h>
#include <float.h>
#include <stdint.h>

// Problem constants
#define BB 2
#define TT 512
#define DM 3584
#define NQ 28
#define NKV 4
#define GRP 7
#define HH 128
#define SCACHE 3584
#define SEQ 4096

#define OUT_ELEMS (BB*TT*DM)
#define KV_ELEMS  (BB*SEQ*NKV*HH)

// Scratch
__device__ float g_q[BB*TT*NQ*HH];
__device__ float g_enc[BB*TT*NQ*HH];
__device__ __half g_kh[KV_ELEMS];
__device__ __half g_vh[KV_ELEMS];

__device__ __forceinline__ void mma_f16(float c[4], const uint32_t a[4], const uint32_t b[2]) {
    asm volatile("mma.sync.aligned.m16n8k16.row.col.f32.f16.f16.f32 "
        "{%0,%1,%2,%3}, {%4,%5,%6,%7}, {%8,%9}, {%0,%1,%2,%3};"
        : "+f"(c[0]), "+f"(c[1]), "+f"(c[2]), "+f"(c[3])
        : "r"(a[0]), "r"(a[1]), "r"(a[2]), "r"(a[3]), "r"(b[0]), "r"(b[1]));
}

__device__ __forceinline__ void ldsm4(uint32_t& r0, uint32_t& r1, uint32_t& r2, uint32_t& r3,
                                      uint32_t addr) {
    asm volatile("ldmatrix.sync.aligned.m8n8.x4.shared.b16 {%0,%1,%2,%3}, [%4];"
        : "=r"(r0), "=r"(r1), "=r"(r2), "=r"(r3) : "r"(addr));
}
__device__ __forceinline__ void ldsm4t(uint32_t& r0, uint32_t& r1, uint32_t& r2, uint32_t& r3,
                                       uint32_t addr) {
    asm volatile("ldmatrix.sync.aligned.m8n8.x4.trans.shared.b16 {%0,%1,%2,%3}, [%4];"
        : "=r"(r0), "=r"(r1), "=r"(r2), "=r"(r3) : "r"(addr));
}

__device__ __forceinline__ uint32_t smem_u32(const void* p) {
    uint32_t a;
    asm("{ .reg .u64 t; cvta.to.shared.u64 t, %1; cvt.u32.u64 %0, t; }" : "=r"(a) : "l"(p));
    return a;
}

__device__ __forceinline__ uint32_t pack_h2(float a, float b) {
    __half2 h = __floats2half2_rn(a, b);
    return *(uint32_t*)&h;
}

// ===========================================================================
// Dense GEMM mainloop — fp16 m16n8k16 + ldmatrix.
// A row-major [128 x K] (lda), B row-major [K x 128] (ldb, stored [n][k]).
// 256 threads, 8 warps, warp tile 32x64. acc[mt 2][nt 8][4].
// ===========================================================================
#define GBK 32
#define GAS 40       // smem stride in halves (80B rows; conflict-free ldmatrix)
#define CHUNKS (DM/GBK)

__device__ __forceinline__ void gemm_f16_mainloop(
    const float* __restrict__ Ag, int lda,
    const float* __restrict__ Bg, int ldb,
    float acc[2][8][4])
{
    __shared__ __align__(16) __half As[128*GAS];
    __shared__ __align__(16) __half Bs[128*GAS];

    int tid = threadIdx.x;
    int wid = tid >> 5, lane = tid & 31;
    int wm = (wid & 3) * 32, wn = (wid >> 2) * 64;

    uint32_t as_b = smem_u32(As), bs_b = smem_u32(Bs);
    // ldmatrix lane address bases
    uint32_t abase = as_b + (uint32_t)((wm + (lane & 7) + ((lane >> 3) & 1) * 8) * GAS
                                       + ((lane >> 4) & 1) * 8) * 2;
    uint32_t bbase = bs_b + (uint32_t)((wn + (lane & 7) + ((lane >> 4) & 1) * 8) * GAS
                                       + ((lane >> 3) & 1) * 8) * 2;

    #pragma unroll
    for (int mt = 0; mt < 2; mt++)
        #pragma unroll
        for (int nt = 0; nt < 8; nt++)
            #pragma unroll
            for (int q = 0; q < 4; q++) acc[mt][nt][q] = 0.f;

    float4 pa[2][2];
    float  pb[2][8];

    // ---- prefetch chunk 0 ----
    #pragma unroll
    for (int it = 0; it < 2; it++) {
        int idx = it * 256 + tid;
        int m = idx >> 2, kq = idx & 3;
        pa[it][0] = *(const float4*)(Ag + (size_t)m * lda + kq * 8);
        pa[it][1] = *(const float4*)(Ag + (size_t)m * lda + kq * 8 + 4);
        int n = idx & 127, k8 = (idx >> 7) * 8;
        #pragma unroll
        for (int j = 0; j < 8; j++)
            pb[it][j] = Bg[(size_t)(k8 + j) * ldb + n];
    }
    // ---- store chunk 0 ----
    #pragma unroll
    for (int it = 0; it < 2; it++) {
        int idx = it * 256 + tid;
        int m = idx >> 2, kq = idx & 3;
        uint4 o;
        o.x = pack_h2(pa[it][0].x, pa[it][0].y);
        o.y = pack_h2(pa[it][0].z, pa[it][0].w);
        o.z = pack_h2(pa[it][1].x, pa[it][1].y);
        o.w = pack_h2(pa[it][1].z, pa[it][1].w);
        *(uint4*)&As[m * GAS + kq * 8] = o;
        int n = idx & 127, k8 = (idx >> 7) * 8;
        uint4 p;
        p.x = pack_h2(pb[it][0], pb[it][1]);
        p.y = pack_h2(pb[it][2], pb[it][3]);
        p.z = pack_h2(pb[it][4], pb[it][5]);
        p.w = pack_h2(pb[it][6], pb[it][7]);
        *(uint4*)&Bs[n * GAS + k8] = p;
    }
    __syncthreads();

    for (int c = 0; c < CHUNKS; c++) {
        // prefetch next chunk into registers
        if (c + 1 < CHUNKS) {
            int k0 = (c + 1) * GBK;
            #pragma unroll
            for (int it = 0; it < 2; it++) {
                int idx = it * 256 + tid;
                int m = idx >> 2, kq = idx & 3;
                pa[it][0] = *(const float4*)(Ag + (size_t)m * lda + k0 + kq * 8);
                pa[it][1] = *(const float4*)(Ag + (size_t)m * lda + k0 + kq * 8 + 4);
                int n = idx & 127, k8 = (idx >> 7) * 8;
                #pragma unroll
                for (int j = 0; j < 8; j++)
                    pb[it][j] = Bg[(size_t)(k0 + k8 + j) * ldb + n];
            }
        }

        // compute: 2 ksteps of k16
        #pragma unroll
        for (int ks = 0; ks < 2; ks++) {
            uint32_t af[2][4];
            #pragma unroll
            for (int mt = 0; mt < 2; mt++)
                ldsm4(af[mt][0], af[mt][1], af[mt][2], af[mt][3],
                      abase + (uint32_t)(mt * 16 * GAS + ks * 16) * 2);
            #pragma unroll
            for (int nt2 = 0; nt2 < 4; nt2++) {
                uint32_t t0, t1, t2, t3;
                ldsm4(t0, t1, t2, t3, bbase + (uint32_t)(nt2 * 16 * GAS + ks * 16) * 2);
                uint32_t lo[2] = {t0, t1}, hi[2] = {t2, t3};
                #pragma unroll
                for (int mt = 0; mt < 2; mt++) {
                    mma_f16(acc[mt][nt2 * 2],     af[mt], lo);
                    mma_f16(acc[mt][nt2 * 2 + 1], af[mt], hi);
                }
            }
        }
        __syncthreads();

        if (c + 1 < CHUNKS) {
            #pragma unroll
            for (int it = 0; it < 2; it++) {
                int idx = it * 256 + tid;
                int m = idx >> 2, kq = idx & 3;
                uint4 o;
                o.x = pack_h2(pa[it][0].x, pa[it][0].y);
                o.y = pack_h2(pa[it][0].z, pa[it][0].w);
                o.z = pack_h2(pa[it][1].x, pa[it][1].y);
                o.w = pack_h2(pa[it][1].z, pa[it][1].w);
                *(uint4*)&As[m * GAS + kq * 8] = o;
                int n = idx & 127, k8 = (idx >> 7) * 8;
                uint4 p;
                p.x = pack_h2(pb[it][0], pb[it][1]);
                p.y = pack_h2(pb[it][2], pb[it][3]);
                p.z = pack_h2(pb[it][4], pb[it][5]);
                p.w = pack_h2(pb[it][6], pb[it][7]);
                *(uint4*)&Bs[n * GAS + k8] = p;
            }
            __syncthreads();
        }
    }
}

// ===========================================================================
// QKV projection
// ===========================================================================
__global__ __launch_bounds__(256, 2) void qkv_mma_kernel(
    const float* __restrict__ x,
    const float* __restrict__ wq, const float* __restrict__ wk,
    const float* __restrict__ wv,
    float* __restrict__ outk, float* __restrict__ outv)
{
    int m0 = blockIdx.x * 128;
    int hz = blockIdx.y;
    const float* Bg;
    if (hz < NQ)          Bg = wq + (size_t)hz * DM * HH;
    else if (hz < NQ+NKV) Bg = wk + (size_t)(hz - NQ) * DM * HH;
    else                  Bg = wv + (size_t)(hz - NQ - NKV) * DM * HH;

    float acc[2][8][4];
    gemm_f16_mainloop(x + (size_t)m0 * DM, DM, Bg, HH, acc);

    int tid = threadIdx.x;
    int wid = tid >> 5, lane = tid & 31;
    int wm = (wid & 3) * 32, wn = (wid >> 2) * 64;
    int g = lane >> 2, tg = lane & 3;

    #pragma unroll
    for (int mt = 0; mt < 2; mt++) {
        #pragma unroll
        for (int h2 = 0; h2 < 2; h2++) {
            int row = wm + mt * 16 + g + h2 * 8;
            int mg = m0 + row;
            int b = mg / TT, t = mg - b * TT;
            float* dst;
            if (hz < NQ)
                dst = g_q + ((size_t)mg * NQ + hz) * HH;
            else if (hz < NQ+NKV)
                dst = outk + (((size_t)(b * SEQ + SCACHE + t)) * NKV + (hz - NQ)) * HH;
            else
                dst = outv + (((size_t)(b * SEQ + SCACHE + t)) * NKV + (hz - NQ - NKV)) * HH;
            #pragma unroll
            for (int nt = 0; nt < 8; nt++) {
                float2 v = make_float2(acc[mt][nt][h2 * 2], acc[mt][nt][h2 * 2 + 1]);
                *(float2*)(dst + wn + nt * 8 + tg * 2) = v;
            }
        }
    }
}

// ===========================================================================
// Output projection
// ===========================================================================
__global__ __launch_bounds__(256, 2) void out_mma_kernel(
    const float* __restrict__ wo, float* __restrict__ out)
{
    int m0 = blockIdx.x * 128;
    int n0 = blockIdx.y * 128;

    float acc[2][8][4];
    gemm_f16_mainloop(g_enc + (size_t)m0 * DM, DM, wo + n0, DM, acc);

    int tid = threadIdx.x;
    int wid = tid >> 5, lane = tid & 31;
    int wm = (wid & 3) * 32, wn = (wid >> 2) * 64;
    int g = lane >> 2, tg = lane & 3;

    #pragma unroll
    for (int mt = 0; mt < 2; mt++) {
        #pragma unroll
        for (int h2 = 0; h2 < 2; h2++) {
            int row = wm + mt * 16 + g + h2 * 8;
            float* dst = out + (size_t)(m0 + row) * DM + n0;
            #pragma unroll
            for (int nt = 0; nt < 8; nt++) {
                float2 v = make_float2(acc[mt][nt][h2 * 2], acc[mt][nt][h2 * 2 + 1]);
                *(float2*)(dst + wn + nt * 8 + tg * 2) = v;
            }
        }
    }
}

// ---------------------------------------------------------------------------
// Cache copy (fp32 outputs)
// ---------------------------------------------------------------------------
__global__ void cache_copy_kernel(const float4* __restrict__ ck,
                                  const float4* __restrict__ cv,
                                  float4* __restrict__ outk,
                                  float4* __restrict__ outv)
{
    const int per_b = SCACHE*NKV*HH/4;
    const int n4 = BB * per_b;
    for (int idx = blockIdx.x*blockDim.x + threadIdx.x; idx < n4;
         idx += gridDim.x*blockDim.x) {
        int b = idx / per_b;
        int r = idx - b*per_b;
        size_t o = (size_t)b*(SEQ*NKV*HH/4) + r;
        outk[o] = ck[idx];
        outv[o] = cv[idx];
    }
}

// ---------------------------------------------------------------------------
// mRoPE in place
// ---------------------------------------------------------------------------
__global__ void rope_kernel(const int* __restrict__ positions,
                            float* __restrict__ outk)
{
    int idx = blockIdx.x*blockDim.x + threadIdx.x;
    if (idx >= BB*TT*64) return;
    int i = idx & 63;
    int t = (idx >> 6) & (TT-1);
    int b = idx >> 15;

    int j = (i < 16) ? 0 : ((i < 40) ? 1 : 2);
    int pos = positions[(j*BB + b)*TT + t];

    double inv = exp2(((double)(-2*i) / 128.0) * 19.931568569324174);
    double ang = (double)pos * inv;
    double sd, cd;
    sincos(ang, &sd, &cd);
    float c = (float)cd, s = (float)sd;
    const float qs = 0.08838834764831845f;

    size_t qbase = ((size_t)(b*TT + t))*NQ*HH;
    #pragma unroll 4
    for (int n = 0; n < NQ; n++) {
        float x1 = g_q[qbase + n*HH + i];
        float x2 = g_q[qbase + n*HH + i + 64];
        g_q[qbase + n*HH + i]      = (x1*c - x2*s)*qs;
        g_q[qbase + n*HH + i + 64] = (x2*c + x1*s)*qs;
    }
    size_t kbase = ((size_t)(b*SEQ + SCACHE + t))*NKV*HH;
    #pragma unroll
    for (int kh = 0; kh < NKV; kh++) {
        float x1 = outk[kbase + kh*HH + i];
        float x2 = outk[kbase + kh*HH + i + 64];
        outk[kbase + kh*HH + i]      = x1*c - x2*s;
        outk[kbase + kh*HH + i + 64] = x2*c + x1*s;
    }
}

// ---------------------------------------------------------------------------
// K/V cache -> fp16 mirrors (after rope)
// ---------------------------------------------------------------------------
__global__ void kv2h_kernel(const float4* __restrict__ k32,
                            const float4* __restrict__ v32,
                            uint2* __restrict__ kh, uint2* __restrict__ vh)
{
    int n4 = KV_ELEMS / 4;
    for (int idx = blockIdx.x*blockDim.x + threadIdx.x; idx < n4;
         idx += gridDim.x*blockDim.x) {
        float4 a = k32[idx];
        float4 b = v32[idx];
        uint2 ka, vb;
        ka.x = pack_h2(a.x, a.y); ka.y = pack_h2(a.z, a.w);
        vb.x = pack_h2(b.x, b.y); vb.y = pack_h2(b.z, b.w);
        kh[idx] = ka;
        vh[idx] = vb;
    }
}

// ===========================================================================
// Flash attention: fp16 K/V pre-converted; ldmatrix (+trans for V);
// P register-resident (C-layout == A-layout trick). fp32 softmax/accum.
// CTA: 64 queries x 1 head x 1 batch; 4 warps, warp owns 16 rows.
// ===========================================================================
#define KSH 136     // smem stride in halves (272B rows; conflict-free)

__global__ __launch_bounds__(128, 3) void attn_f16_kernel()
{
    __shared__ __align__(16) __half Kc[64*KSH];
    __shared__ __align__(16) __half Vs[64*KSH];

    int t0 = blockIdx.x * 64;
    int n  = blockIdx.y;
    int b  = blockIdx.z;
    int kh = n / GRP;
    int tid = threadIdx.x, wid = tid >> 5, lane = tid & 31;
    int g = lane >> 2, tg = lane & 3;
    int wm = wid * 16;
    int r0 = wm + g, r1 = r0 + 8;

    uint32_t kc_b = smem_u32(Kc), vs_b = smem_u32(Vs);

    // K ldmatrix base (non-trans): tiles (key, h)
    uint32_t kaddr = kc_b + (uint32_t)(((lane & 7) + ((lane >> 4) & 1) * 8) * KSH
                                       + ((lane >> 3) & 1) * 8) * 2;
    // V ldmatrix base (trans): rows = keys, cols = h
    uint32_t vaddr = vs_b + (uint32_t)(((lane & 7) + ((lane >> 3) & 1) * 8) * KSH
                                       + ((lane >> 4) & 1) * 8) * 2;

    // Q fragments (fp16 packed)
    uint32_t qa[8][4];
    {
        const float* q0 = g_q + (((size_t)(b*TT + t0 + r0))*NQ + n)*HH;
        const float* q1 = g_q + (((size_t)(b*TT + t0 + r1))*NQ + n)*HH;
        #pragma unroll
        for (int ks = 0; ks < 8; ks++) {
            float2 v0 = *(const float2*)(q0 + ks*16 + 2*tg);
            float2 v1 = *(const float2*)(q1 + ks*16 + 2*tg);
            float2 v2 = *(const float2*)(q0 + ks*16 + 2*tg + 8);
            float2 v3 = *(const float2*)(q1 + ks*16 + 2*tg + 8);
            qa[ks][0] = pack_h2(v0.x, v0.y);
            qa[ks][1] = pack_h2(v1.x, v1.y);
            qa[ks][2] = pack_h2(v2.x, v2.y);
            qa[ks][3] = pack_h2(v3.x, v3.y);
        }
    }

    float oacc[16][4];
    #pragma unroll
    for (int nt = 0; nt < 16; nt++)
        #pragma unroll
        for (int q = 0; q < 4; q++) oacc[nt][q] = 0.f;
    float mrow[2] = {-FLT_MAX, -FLT_MAX};
    float lrow[2] = {0.f, 0.f};

    int nchunks = (SCACHE + t0 + 64) >> 6;

    for (int ch = 0; ch < nchunks; ch++) {
        int s0 = ch * 64;
        __syncthreads();   // prior chunk's smem reads done

        // ---- stage K and V chunks: plain fp16 16B copies ----
        {
            const __half* ksrc = &g_kh[(((size_t)(b*SEQ + s0))*NKV + kh)*HH];
            const __half* vsrc = &g_vh[(((size_t)(b*SEQ + s0))*NKV + kh)*HH];
            #pragma unroll
            for (int it = 0; it < 8; it++) {
                int idx = it * 128 + tid;
                int row = idx >> 4, c16 = (idx & 15) * 8;
                *(uint4*)&Kc[row * KSH + c16] =
                    *(const uint4*)&ksrc[(size_t)row * (NKV*HH) + c16];
                *(uint4*)&Vs[row * KSH + c16] =
                    *(const uint4*)&vsrc[(size_t)row * (NKV*HH) + c16];
            }
        }
        __syncthreads();

        // ---- S = Q K^T : warp computes 16x64 ----
        float sacc[8][4];
        #pragma unroll
        for (int nt = 0; nt < 8; nt++)
            #pragma unroll
            for (int q = 0; q < 4; q++) sacc[nt][q] = 0.f;

        #pragma unroll
        for (int ks = 0; ks < 8; ks++) {
            #pragma unroll
            for (int kb = 0; kb < 4; kb++) {
                uint32_t b0, b1, b2, b3;
                ldsm4(b0, b1, b2, b3, kaddr + (uint32_t)(kb*16*KSH + ks*16)*2);
                uint32_t lo[2] = {b0, b1}, hi[2] = {b2, b3};
                mma_f16(sacc[2*kb],   qa[ks], lo);
                mma_f16(sacc[2*kb+1], qa[ks], hi);
            }
        }

        // ---- causal mask (final chunk only) ----
        if (ch == nchunks - 1) {
            int smax0 = SCACHE + t0 + r0;
            int smax1 = SCACHE + t0 + r1;
            #pragma unroll
            for (int nt = 0; nt < 8; nt++) {
                int col = s0 + nt*8 + 2*tg;
                if (col     > smax0) sacc[nt][0] = -FLT_MAX;
                if (col + 1 > smax0) sacc[nt][1] = -FLT_MAX;
                if (col     > smax1) sacc[nt][2] = -FLT_MAX;
                if (col + 1 > smax1) sacc[nt][3] = -FLT_MAX;
            }
        }

        // ---- online softmax; P packed directly into PV A-fragments ----
        uint32_t pfrag[4][4];
        #pragma unroll
        for (int hr = 0; hr < 2; hr++) {
            float mx = -FLT_MAX;
            #pragma unroll
            for (int nt = 0; nt < 8; nt++)
                mx = fmaxf(mx, fmaxf(sacc[nt][hr*2], sacc[nt][hr*2+1]));
            mx = fmaxf(mx, __shfl_xor_sync(0xffffffffu, mx, 1));
            mx = fmaxf(mx, __shfl_xor_sync(0xffffffffu, mx, 2));
            float mnew = fmaxf(mrow[hr], mx);
            float corr = __expf(mrow[hr] - mnew);
            mrow[hr] = mnew;
            float rs = 0.f;
            #pragma unroll
            for (int nt = 0; nt < 8; nt++) {
                float p0 = __expf(sacc[nt][hr*2]   - mnew);
                float p1 = __expf(sacc[nt][hr*2+1] - mnew);
                rs += p0 + p1;
                pfrag[nt >> 1][(nt & 1) * 2 + hr] = pack_h2(p0, p1);
            }
            rs += __shfl_xor_sync(0xffffffffu, rs, 1);
            rs += __shfl_xor_sync(0xffffffffu, rs, 2);
            lrow[hr] = lrow[hr]*corr + rs;
            #pragma unroll
            for (int nt = 0; nt < 16; nt++) {
                oacc[nt][hr*2]   *= corr;
                oacc[nt][hr*2+1] *= corr;
            }
        }

        // ---- O += P V : B-frags via ldmatrix.trans on row-major V ----
        #pragma unroll
        for (int kk = 0; kk < 4; kk++) {
            #pragma unroll
            for (int nb = 0; nb < 8; nb++) {
                uint32_t t0v, t1v, t2v, t3v;
                ldsm4t(t0v, t1v, t2v, t3v,
                       vaddr + (uint32_t)(kk*16*KSH + nb*16)*2);
                uint32_t lo[2] = {t0v, t1v}, hi[2] = {t2v, t3v};
                mma_f16(oacc[2*nb],   pfrag[kk], lo);
                mma_f16(oacc[2*nb+1], pfrag[kk], hi);
            }
        }
    }

    // ---- finalize ----
    float inv0 = 1.f / lrow[0];
    float inv1 = 1.f / lrow[1];
    float* e0 = g_enc + (((size_t)(b*TT + t0 + r0))*NQ + n)*HH;
    float* e1 = g_enc + (((size_t)(b*TT + t0 + r1))*NQ + n)*HH;
    #pragma unroll
    for (int nt = 0; nt < 16; nt++) {
        int col = nt*8 + 2*tg;
        *(float2*)(e0 + col) = make_float2(oacc[nt][0]*inv0, oacc[nt][1]*inv0);
        *(float2*)(e1 + col) = make_float2(oacc[nt][2]*inv1, oacc[nt][3]*inv1);
    }
}

// ---------------------------------------------------------------------------
// Launch
// ---------------------------------------------------------------------------
extern "C" void kernel_launch(void* const* d_in, const int* in_sizes, int n_in,
                              void* d_out, int out_size)
{
    const float* x         = (const float*)d_in[0];
    const int*   positions = (const int*)d_in[1];
    const float* cache_k   = (const float*)d_in[3];
    const float* cache_v   = (const float*)d_in[4];
    const float* wq        = (const float*)d_in[5];
    const float* wk        = (const float*)d_in[6];
    const float* wv        = (const float*)d_in[7];
    const float* wo        = (const float*)d_in[8];

    float* out  = (float*)d_out;
    float* outk = out + (size_t)OUT_ELEMS;
    float* outv = outk + (size_t)KV_ELEMS;

    __half* kh_p; __half* vh_p;
    cudaGetSymbolAddress((void**)&kh_p, g_kh);
    cudaGetSymbolAddress((void**)&vh_p, g_vh);

    cache_copy_kernel<<<1024, 256>>>((const float4*)cache_k, (const float4*)cache_v,
                                     (float4*)outk, (float4*)outv);
    qkv_mma_kernel<<<dim3(8, 36), 256>>>(x, wq, wk, wv, outk, outv);
    rope_kernel<<<(BB*TT*64 + 255)/256, 256>>>(positions, outk);
    kv2h_kernel<<<2048, 256>>>((const float4*)outk, (const float4*)outv,
                               (uint2*)kh_p, (uint2*)vh_p);
    attn_f16_kernel<<<dim3(TT/64, NQ, BB), 128>>>();
    out_mma_kernel<<<dim3(8, 28), 256>>>(wo, out);
}